// round 12
// baseline (speedup 1.0000x reference)
#include <cuda_runtime.h>
#include <math.h>
#include <stdint.h>

#define BB 128
#define LL 256
#define NNB 8
#define FF 200
#define F3 600
#define BL (BB*LL)
#define RROUNDS 2
#define TSTEPS 2
#define KPAD 224
#define NCH 7

__device__ float g_molW[BB*FF];
__device__ float g_sst[BL*F3];
__device__ float g_ctxf[BL*FF];
__device__ float g_gi[BL*F3];
__device__ float g_gh[BL*F3];
__device__ float g_dec[BL*64];
__device__ float g_decb[64];
__device__ float g_rb[RROUNDS*F3];

#define A8PL ((size_t)BL*KPAD)
#define M8PL ((size_t)BB*KPAD)
__device__ __align__(16) int8_t g_h8[2*BL*KPAD];
__device__ __align__(16) int8_t g_a8[2*BL*KPAD];
__device__ __align__(16) int8_t g_c8[2*BL*KPAD];
__device__ __align__(16) int8_t g_mf8[2*BB*KPAD];
__device__ float g_sH[BL];
__device__ float g_sA[BL];
__device__ float g_sC[BL];
__device__ float g_sMF[BB];

#define WROWS 5264
#define W8PL ((size_t)WROWS*KPAD)
__device__ __align__(16) int8_t g_w8[2*WROWS*KPAD];
__device__ float g_sW[WROWS];

#define W_MOL0 0
#define W_MOL1 200
#define W_MGI  400
#define W_MGH  1000
#define W_RND(d) (1600 + (d)*1800)
#define W_DEC  5200
#define W_TOT  5259
#define NSEG 17

__device__ __forceinline__ uint32_t smem_u32(const void* p) {
    uint32_t a;
    asm("{ .reg .u64 t; cvta.to.shared.u64 t, %1; cvt.u32.u64 %0, t; }"
        : "=r"(a) : "l"(p));
    return a;
}
__device__ __forceinline__ void ldsm4(uint32_t* r, uint32_t a) {
    asm volatile("ldmatrix.sync.aligned.m8n8.x4.shared.b16 {%0,%1,%2,%3}, [%4];"
        : "=r"(r[0]), "=r"(r[1]), "=r"(r[2]), "=r"(r[3]) : "r"(a));
}
__device__ __forceinline__ void imma(int* c, const uint32_t* a, const uint32_t* b) {
    asm volatile("mma.sync.aligned.m16n8k32.row.col.s32.s8.s8.s32 "
        "{%0,%1,%2,%3}, {%4,%5,%6,%7}, {%8,%9}, {%0,%1,%2,%3};"
        : "+r"(c[0]), "+r"(c[1]), "+r"(c[2]), "+r"(c[3])
        : "r"(a[0]), "r"(a[1]), "r"(a[2]), "r"(a[3]), "r"(b[0]), "r"(b[1]));
}
__device__ __forceinline__ void cpa16(uint32_t dst, const void* src, int srcSize) {
    asm volatile("cp.async.cg.shared.global [%0], [%1], 16, %2;"
        :: "r"(dst), "l"(src), "r"(srcSize));
}
__device__ __forceinline__ void cp_commit() {
    asm volatile("cp.async.commit_group;" ::: "memory");
}
__device__ __forceinline__ void cp_wait0() {
    asm volatile("cp.async.wait_group 0;" ::: "memory");
}
__device__ __forceinline__ void quantw(float v, float inv, int8_t* q1p, int8_t* q2p) {
    float q1 = rintf(v * inv);
    q1 = fminf(fmaxf(q1, -127.f), 127.f);
    float q2 = rintf((v * inv - q1) * 128.f);
    q2 = fminf(fmaxf(q2, -127.f), 127.f);
    *q1p = (int8_t)q1;
    *q2p = (int8_t)q2;
}
__device__ __forceinline__ float wmax32(float v) {
    #pragma unroll
    for (int o = 16; o > 0; o >>= 1) v = fmaxf(v, __shfl_xor_sync(0xffffffffu, v, o));
    return v;
}

// ---------------- weight prep: warp-per-row quantization ----------------
struct Seg { const float* src; int stride; int dst; int pad; };
struct SegTab { Seg s[NSEG]; };

__global__ void prep_w8(SegTab tab)
{
    int warp = threadIdx.x >> 5, lane = threadIdx.x & 31;
    int r = blockIdx.x * 8 + warp;
    if (r >= W_TOT) return;
    int si = 0;
    #pragma unroll
    for (int i = 1; i < NSEG; i++) if (r >= tab.s[i].dst) si = i;
    const float* src = tab.s[si].src + (size_t)(r - tab.s[si].dst) * tab.s[si].stride;
    float vals[7];
    float mx = 0.f;
    #pragma unroll
    for (int j = 0; j < 7; j++) {
        int f = lane + j * 32;
        vals[j] = (f < FF) ? src[f] : 0.f;
        mx = fmaxf(mx, fabsf(vals[j]));
    }
    mx = wmax32(mx);
    float inv = (mx > 0.f) ? 127.f / mx : 0.f;
    #pragma unroll
    for (int j = 0; j < 7; j++) {
        int f = lane + j * 32;
        if (f < FF)
            quantw(vals[j], inv, &g_w8[(size_t)r * KPAD + f], &g_w8[W8PL + (size_t)r * KPAD + f]);
    }
    if (lane == 0) g_sW[r] = mx / 127.f;
}

__global__ void prep_small(const float* __restrict__ molf,
                           const float* __restrict__ ab, const float* __restrict__ bb,
                           const float* __restrict__ align_b, const float* __restrict__ attend_b)
{
    if (blockIdx.x < 16) {
        int warp = threadIdx.x >> 5, lane = threadIdx.x & 31;
        int r = blockIdx.x * 8 + warp;
        const float* src = molf + (size_t)r * FF;
        float vals[7]; float mx = 0.f;
        #pragma unroll
        for (int j = 0; j < 7; j++) {
            int f = lane + j * 32;
            vals[j] = (f < FF) ? src[f] : 0.f;
            mx = fmaxf(mx, fabsf(vals[j]));
        }
        mx = wmax32(mx);
        float inv = (mx > 0.f) ? 127.f / mx : 0.f;
        #pragma unroll
        for (int j = 0; j < 7; j++) {
            int f = lane + j * 32;
            if (f < FF)
                quantw(vals[j], inv, &g_mf8[(size_t)r * KPAD + f], &g_mf8[M8PL + (size_t)r * KPAD + f]);
        }
        if (lane == 0) g_sMF[r] = mx / 127.f;
        return;
    }
    int i = (blockIdx.x - 16) * 256 + threadIdx.x;
    if (i < 64) {
        float v = 0.f;
        if (i < 39) v = ab[i];
        else if (i < 49) v = bb[i - 39];
        g_decb[i] = v;
    }
    int j = i - 64;
    if (j >= 0 && j < RROUNDS * F3) {
        int d = j / F3, f = j - d * F3;
        float v = 0.f;
        if (f < 200) v = align_b[d * FF + f];
        else if (f >= 400) v = attend_b[d * FF + f - 400];
        g_rb[j] = v;
    }
}

// ---------------- int8 split GEMM: CTA 128x64, warp 32x32 ----------------
#define PITCH8 48
#define RA2 6144
#define RB1 12288
#define RB2 15360
#define STG8 18432
#define TG8_SMEM (2*STG8)

template<int ACT>
__global__ __launch_bounds__(256, 2) void tgemm8(
    const int8_t* __restrict__ Aq0, const float* __restrict__ sA0, int woff0,
    const float* __restrict__ bias0, float* __restrict__ C0,
    int M, int Nn, const float* __restrict__ rowAdd, int rpg, long aPl0,
    const int8_t* Aq1, const float* sA1, int woff1,
    const float* bias1, float* C1)
{
    extern __shared__ __align__(16) char sm[];
    const uint32_t sb = smem_u32(sm);
    const int tid = threadIdx.x, lane = tid & 31, wid = tid >> 5;
    const int bm = blockIdx.y * 128, bn = blockIdx.x * 64;
    const int wm = (wid & 3) * 32, wn = (wid >> 2) * 32;

    const int8_t* Aq = Aq0; const float* sA = sA0; int woff = woff0;
    const float* bias = bias0; float* C = C0; long aPl = aPl0;
    if (blockIdx.z == 1) { Aq = Aq1; sA = sA1; woff = woff1; bias = bias1; C = C1; }

    int acc0[2][4][4], acc1[2][4][4];
    #pragma unroll
    for (int i = 0; i < 2; i++)
        #pragma unroll
        for (int j = 0; j < 4; j++)
            #pragma unroll
            for (int k = 0; k < 4; k++) { acc0[i][j][k] = 0; acc1[i][j][k] = 0; }

    const int arow = tid >> 1, aoff = (tid & 1) * 16;
    const int8_t* pA1g = Aq + (size_t)(bm + arow) * KPAD + aoff;
    const int8_t* pA2g = pA1g + aPl;
    const uint32_t dA = (uint32_t)(arow * PITCH8) + aoff;
    const int brow = tid >> 1;
    const int nb = bn + brow;
    const int vB = (tid < 128 && nb < Nn) ? 16 : 0;
    const int nbs = (nb < Nn) ? nb : 0;
    const int8_t* pB1g = g_w8 + (size_t)(woff + nbs) * KPAD + aoff;
    const int8_t* pB2g = pB1g + W8PL;
    const uint32_t dB = (uint32_t)(brow * PITCH8) + aoff;

    auto stage_load = [&](int t, int st) {
        const int kb = t * 32;
        const uint32_t s = sb + st * STG8;
        cpa16(s + dA,        pA1g + kb, 16);
        cpa16(s + RA2 + dA,  pA2g + kb, 16);
        if (tid < 128) {
            cpa16(s + RB1 + dB, pB1g + kb, vB);
            cpa16(s + RB2 + dB, pB2g + kb, vB);
        }
    };

    stage_load(0, 0);
    cp_commit();

    const int la = (lane & 7) + ((lane >> 3) & 1) * 8;
    const int ka = (lane >> 4) * 16;
    const uint32_t aBase = (uint32_t)((wm + la) * PITCH8) + ka;
    const int lb = (lane & 7) + (lane >> 4) * 8;
    const int kb2 = ((lane >> 3) & 1) * 16;
    const uint32_t bBase = RB1 + (uint32_t)((wn + lb) * PITCH8) + kb2;

    for (int t = 0; t < NCH; t++) {
        cp_wait0();
        __syncthreads();
        if (t + 1 < NCH) { stage_load(t + 1, (t + 1) & 1); cp_commit(); }
        const uint32_t s = sb + (t & 1) * STG8;

        uint32_t a1[2][4], a2[2][4], b1[2][4], b2[2][4];
        ldsm4(a1[0], s + aBase);
        ldsm4(a1[1], s + aBase + 16 * PITCH8);
        ldsm4(a2[0], s + RA2 + aBase);
        ldsm4(a2[1], s + RA2 + aBase + 16 * PITCH8);
        ldsm4(b1[0], s + bBase);
        ldsm4(b1[1], s + bBase + 16 * PITCH8);
        ldsm4(b2[0], s + (RB2 - RB1) + bBase);
        ldsm4(b2[1], s + (RB2 - RB1) + bBase + 16 * PITCH8);

        #pragma unroll
        for (int mi = 0; mi < 2; mi++)
            #pragma unroll
            for (int nj = 0; nj < 4; nj++) {
                const uint32_t* p1 = &b1[nj >> 1][(nj & 1) * 2];
                const uint32_t* p2 = &b2[nj >> 1][(nj & 1) * 2];
                imma(acc0[mi][nj], a1[mi], p1);
                imma(acc1[mi][nj], a1[mi], p2);
                imma(acc1[mi][nj], a2[mi], p1);
            }
        __syncthreads();
    }

    const float* sWp = g_sW + woff;
    const int lr = lane >> 2, lc = (lane & 3) * 2;
    #pragma unroll
    for (int mi = 0; mi < 2; mi++) {
        #pragma unroll
        for (int hh = 0; hh < 2; hh++) {
            int m = bm + wm + mi * 16 + hh * 8 + lr;
            float sa = sA[m];
            const float* ra = rowAdd ? (rowAdd + (size_t)(m / rpg) * Nn) : nullptr;
            float* crow = C + (size_t)m * Nn;
            #pragma unroll
            for (int nj = 0; nj < 4; nj++) {
                int n = bn + wn + nj * 8 + lc;
                if (n >= Nn) continue;
                float f0 = (float)acc0[mi][nj][hh * 2 + 0]
                         + (float)acc1[mi][nj][hh * 2 + 0] * (1.f / 128.f);
                float f1 = (float)acc0[mi][nj][hh * 2 + 1]
                         + (float)acc1[mi][nj][hh * 2 + 1] * (1.f / 128.f);
                float v0 = sa * sWp[n] * f0;
                float v1 = sa * sWp[n + 1] * f1;
                if (bias) { v0 += bias[n]; v1 += bias[n + 1]; }
                if (ra)   { v0 += ra[n];   v1 += ra[n + 1]; }
                if (ACT == 1) { v0 = (v0 > 0.f) ? v0 : expm1f(v0);
                                v1 = (v1 > 0.f) ? v1 : expm1f(v1); }
                *(float2*)&crow[n] = make_float2(v0, v1);
            }
        }
    }
}

// ---------------- mol phase init ----------------
__global__ __launch_bounds__(256) void mol_pre_kernel(
    const float* __restrict__ molf, const float* __restrict__ actf)
{
    int b = blockIdx.x;
    int tid = threadIdx.x;
    __shared__ float dots[LL];
    __shared__ float red[16];
    const float* mf = molf + (size_t)b * FF;
    int lane = tid & 31, warp = tid >> 5;

    for (int l = warp; l < LL; l += 8) {
        const float* af = actf + ((size_t)b * LL + l) * FF;
        float s = 0.f;
        for (int f = lane; f < FF; f += 32) s += mf[f] * af[f];
        #pragma unroll
        for (int o = 16; o > 0; o >>= 1) s += __shfl_xor_sync(0xffffffffu, s, o);
        if (lane == 0) dots[l] = s;
    }
    __syncthreads();

    float v = dots[tid];
    float m = wmax32(v);
    if (lane == 0) red[warp] = m;
    __syncthreads();
    float mx = red[0];
    #pragma unroll
    for (int i = 1; i < 8; i++) mx = fmaxf(mx, red[i]);
    float e = expf(v - mx);
    float s = e;
    #pragma unroll
    for (int o = 16; o > 0; o >>= 1) s += __shfl_xor_sync(0xffffffffu, s, o);
    if (lane == 0) red[8 + warp] = s;
    __syncthreads();
    float tot = 0.f;
    #pragma unroll
    for (int i = 0; i < 8; i++) tot += red[8 + i];
    __syncthreads();
    dots[tid] = e / tot;
    __syncthreads();

    for (int l = warp; l < LL; l += 8) {
        float w = dots[l];
        const float* af = actf + ((size_t)b * LL + l) * FF;
        float vals[7]; float vm = 0.f;
        #pragma unroll
        for (int j = 0; j < 7; j++) {
            int f = lane + j * 32;
            float x = 0.f;
            if (f < FF) x = w * mf[f] + af[f];
            vals[j] = x;
            vm = fmaxf(vm, fabsf(x));
        }
        vm = wmax32(vm);
        float inv = (vm > 0.f) ? 127.f / vm : 0.f;
        size_t rbase = ((size_t)b * LL + l) * KPAD;
        #pragma unroll
        for (int j = 0; j < 7; j++) {
            int f = lane + j * 32;
            if (f < FF) quantw(vals[j], inv, &g_h8[rbase + f], &g_h8[A8PL + rbase + f]);
        }
        if (lane == 0) g_sH[(size_t)b * LL + l] = vm / 127.f;
    }
}

// ---------------- quantize fp32 ctx -> c planes ----------------
__global__ __launch_bounds__(256) void quant_ctx()
{
    int warp = threadIdx.x >> 5, lane = threadIdx.x & 31;
    int r = blockIdx.x * 8 + warp;
    const float* src = g_ctxf + (size_t)r * FF;
    float vals[7]; float mx = 0.f;
    #pragma unroll
    for (int j = 0; j < 7; j++) {
        int f = lane + j * 32;
        vals[j] = (f < FF) ? src[f] : 0.f;
        mx = fmaxf(mx, fabsf(vals[j]));
    }
    mx = wmax32(mx);
    float inv = (mx > 0.f) ? 127.f / mx : 0.f;
    size_t rbase = (size_t)r * KPAD;
    #pragma unroll
    for (int j = 0; j < 7; j++) {
        int f = lane + j * 32;
        if (f < FF) quantw(vals[j], inv, &g_c8[rbase + f], &g_c8[A8PL + rbase + f]);
    }
    if (lane == 0) g_sC[r] = mx / 127.f;
}

// ---------------- GRU combine: warp-per-row ----------------
__global__ __launch_bounds__(256) void gru8(
    const float* __restrict__ gi, const float* __restrict__ gh,
    const int8_t* __restrict__ hq, const float* __restrict__ sHin, int writeH)
{
    int warp = threadIdx.x >> 5, lane = threadIdx.x & 31;
    int m = blockIdx.x * 8 + warp;
    float sh = sHin[m];
    size_t b3 = (size_t)m * F3;
    size_t rbase = (size_t)m * KPAD;
    float vo[7]; float mo = 0.f, ma = 0.f;
    #pragma unroll
    for (int j = 0; j < 7; j++) {
        int f = lane + j * 32;
        float o = 0.f;
        if (f < FF) {
            float ir = gi[b3 + f], iz = gi[b3 + FF + f], in_ = gi[b3 + 2 * FF + f];
            float hr = gh[b3 + f], hz = gh[b3 + FF + f], hn = gh[b3 + 2 * FF + f];
            float r = 1.f / (1.f + expf(-(ir + hr)));
            float z = 1.f / (1.f + expf(-(iz + hz)));
            float n = tanhf(in_ + r * hn);
            float h = sh * ((float)hq[rbase + f] + (float)hq[A8PL + rbase + f] * (1.f / 128.f));
            o = (1.f - z) * n + z * h;
            mo = fmaxf(mo, fabsf(o));
            ma = fmaxf(ma, o);
        }
        vo[j] = o;
    }
    mo = wmax32(mo);
    ma = fmaxf(wmax32(ma), 0.f);
    float invO = (mo > 0.f) ? 127.f / mo : 0.f;
    float invA = (ma > 0.f) ? 127.f / ma : 0.f;
    #pragma unroll
    for (int j = 0; j < 7; j++) {
        int f = lane + j * 32;
        if (f < FF) {
            if (writeH) quantw(vo[j], invO, &g_h8[rbase + f], &g_h8[A8PL + rbase + f]);
            quantw(fmaxf(vo[j], 0.f), invA, &g_a8[rbase + f], &g_a8[A8PL + rbase + f]);
        }
    }
    if (lane == 0) {
        if (writeH) g_sH[m] = mo / 127.f;
        g_sA[m] = ma / 127.f;
    }
}

// ---------------- neighbor attention context ----------------
__global__ __launch_bounds__(256) void attn_ctx8(
    const float* __restrict__ sst, const int* __restrict__ deg)
{
    int bl = blockIdx.x;
    int b = bl >> 8;
    int tid = threadIdx.x;
    int lane = tid & 31, warp = tid >> 5;
    __shared__ int sidx[NNB];
    __shared__ float wmax8[8];
    if (tid < NNB) sidx[tid] = deg[(size_t)bl * NNB + tid];
    __syncthreads();

    float c = 0.f;
    if (tid < FF) {
        int f = tid;
        float s1v = sst[(size_t)bl * F3 + f];
        float sc[NNB];
        float mx = -3.4e38f;
        #pragma unroll
        for (int n = 0; n < NNB; n++) {
            int j = sidx[n];
            float v = s1v + sst[((size_t)b * LL + j) * F3 + 200 + f];
            v = (v >= 0.f) ? v : 0.01f * v;
            if (j == LL - 1) v += -9e8f;
            sc[n] = v;
            mx = fmaxf(mx, v);
        }
        float sum = 0.f;
        #pragma unroll
        for (int n = 0; n < NNB; n++) { sc[n] = expf(sc[n] - mx); sum += sc[n]; }
        float inv = 1.f / sum;
        #pragma unroll
        for (int n = 0; n < NNB; n++) {
            int j = sidx[n];
            if (j != LL - 1)
                c += sc[n] * inv * sst[((size_t)b * LL + j) * F3 + 400 + f];
        }
        c = (c > 0.f) ? c : expm1f(c);
    }
    float am = (tid < FF) ? fabsf(c) : 0.f;
    am = wmax32(am);
    if (lane == 0) wmax8[warp] = am;
    __syncthreads();
    float mx2 = wmax8[0];
    #pragma unroll
    for (int i = 1; i < 8; i++) mx2 = fmaxf(mx2, wmax8[i]);
    float invq = (mx2 > 0.f) ? 127.f / mx2 : 0.f;
    if (tid < FF) {
        size_t rbase = (size_t)bl * KPAD;
        quantw(c, invq, &g_c8[rbase + tid], &g_c8[A8PL + rbase + tid]);
    }
    if (tid == 0) g_sC[bl] = mx2 / 127.f;
}

// ---------------- decoders ----------------
__device__ __forceinline__ void seg_softmax_acc(const float* v, float* y, int lo, int hi) {
    float m = -3.4e38f;
    for (int i = lo; i < hi; i++) m = fmaxf(m, v[i]);
    float s = 0.f;
    for (int i = lo; i < hi; i++) s += expf(v[i] - m);
    float inv = 1.f / s;
    for (int i = lo; i < hi; i++) y[i] += expf(v[i] - m) * inv;
}
__device__ __forceinline__ float sigf(float x) { return 1.f / (1.f + expf(-x)); }

__global__ __launch_bounds__(256) void atom_act_kernel(
    const float* __restrict__ dec, float* __restrict__ out, int rows)
{
    int m = blockIdx.x * blockDim.x + threadIdx.x;
    if (m >= rows) return;
    const float* x = dec + (size_t)m * 64;
    float v[39], y[39];
    #pragma unroll
    for (int i = 0; i < 39; i++) { v[i] = x[i]; y[i] = 0.f; }
    seg_softmax_acc(v, y, 0, 16);
    seg_softmax_acc(v, y, 16, 22);
    seg_softmax_acc(v, y, 24, 30);
    seg_softmax_acc(v, y, 31, 36);
    y[24] += fmaxf(v[24], 0.f);
    y[30] += sigf(v[30]);
    y[36] += sigf(v[36]);
    y[37] += sigf(v[37]);
    y[38] += sigf(v[38]);
    float* o = out + (size_t)m * 39;
    #pragma unroll
    for (int i = 0; i < 39; i++) o[i] = y[i];
}

__global__ __launch_bounds__(256) void bond_act_kernel(
    const float* __restrict__ dec, const int* __restrict__ deg,
    float* __restrict__ out, int total)
{
    int id = blockIdx.x * blockDim.x + threadIdx.x;
    if (id >= total) return;
    int bl = id / NNB;
    int b = bl >> 8;
    int j = deg[id];
    const float* a = dec + (size_t)bl * 64 + 39;
    const float* c = dec + ((size_t)b * LL + j) * 64 + 49;
    float v[10], y[10];
    #pragma unroll
    for (int k = 0; k < 10; k++) { v[k] = a[k] + c[k]; y[k] = 0.f; }
    seg_softmax_acc(v, y, 0, 4);
    seg_softmax_acc(v, y, 6, 10);
    y[4] += sigf(v[4]);
    y[5] += sigf(v[5]);
    float* o = out + (size_t)id * 10;
    #pragma unroll
    for (int k = 0; k < 10; k++) o[k] = y[k];
}

// ---------------- host ----------------
static inline dim3 tg_grid(int M, int N, int z = 1) {
    return dim3((N + 63) / 64, M / 128, z);
}

extern "C" void kernel_launch(void* const* d_in, const int* in_sizes, int n_in,
                              void* d_out, int out_size)
{
    const int*   deg        = (const int*)  d_in[2];
    const float* molf       = (const float*)d_in[5];
    const float* actf       = (const float*)d_in[6];
    const float* atom_fc_w  = (const float*)d_in[7];
    const float* atom_fc_b  = (const float*)d_in[8];
    const float* bond_fc_w  = (const float*)d_in[9];
    const float* bond_fc_b  = (const float*)d_in[10];
    const float* align_w    = (const float*)d_in[11];
    const float* align_b    = (const float*)d_in[12];
    const float* attend_w   = (const float*)d_in[13];
    const float* attend_b   = (const float*)d_in[14];
    const float* gru_wih    = (const float*)d_in[15];
    const float* gru_whh    = (const float*)d_in[16];
    const float* gru_bih    = (const float*)d_in[17];
    const float* gru_bhh    = (const float*)d_in[18];
    const float* mol_al_w   = (const float*)d_in[19];
    const float* mol_al_b   = (const float*)d_in[20];
    const float* mgru_wih   = (const float*)d_in[21];
    const float* mgru_whh   = (const float*)d_in[22];
    const float* mgru_bih   = (const float*)d_in[23];
    const float* mgru_bhh   = (const float*)d_in[24];
    float* out = (float*)d_out;

    float *p_molW, *p_sst, *p_ctxf, *p_gi, *p_gh, *p_dec, *p_decb, *p_rb;
    float *p_sH, *p_sA, *p_sC, *p_sMF;
    int8_t *p_h8, *p_a8, *p_c8, *p_mf8;
    cudaGetSymbolAddress((void**)&p_molW, g_molW);
    cudaGetSymbolAddress((void**)&p_sst,  g_sst);
    cudaGetSymbolAddress((void**)&p_ctxf, g_ctxf);
    cudaGetSymbolAddress((void**)&p_gi,   g_gi);
    cudaGetSymbolAddress((void**)&p_gh,   g_gh);
    cudaGetSymbolAddress((void**)&p_dec,  g_dec);
    cudaGetSymbolAddress((void**)&p_decb, g_decb);
    cudaGetSymbolAddress((void**)&p_rb,   g_rb);
    cudaGetSymbolAddress((void**)&p_sH,   g_sH);
    cudaGetSymbolAddress((void**)&p_sA,   g_sA);
    cudaGetSymbolAddress((void**)&p_sC,   g_sC);
    cudaGetSymbolAddress((void**)&p_sMF,  g_sMF);
    cudaGetSymbolAddress((void**)&p_h8,   g_h8);
    cudaGetSymbolAddress((void**)&p_a8,   g_a8);
    cudaGetSymbolAddress((void**)&p_c8,   g_c8);
    cudaGetSymbolAddress((void**)&p_mf8,  g_mf8);

    cudaFuncSetAttribute(tgemm8<0>, cudaFuncAttributeMaxDynamicSharedMemorySize, TG8_SMEM);
    cudaFuncSetAttribute(tgemm8<1>, cudaFuncAttributeMaxDynamicSharedMemorySize, TG8_SMEM);

    {
        SegTab tab;
        int i = 0;
        auto add = [&](const float* s, int st, int dst) {
            tab.s[i].src = s; tab.s[i].stride = st; tab.s[i].dst = dst; tab.s[i].pad = 0; i++;
        };
        add(mol_al_w,      2*FF, W_MOL0);
        add(mol_al_w + FF, 2*FF, W_MOL1);
        add(mgru_wih,      FF,   W_MGI);
        add(mgru_whh,      FF,   W_MGH);
        for (int d = 0; d < RROUNDS; d++) {
            const float* aw = align_w + (size_t)d * FF * 2 * FF;
            add(aw,                             2*FF, W_RND(d) + 0);
            add(aw + FF,                        2*FF, W_RND(d) + 200);
            add(attend_w + (size_t)d * FF * FF, FF,   W_RND(d) + 400);
            add(gru_wih + (size_t)d * F3 * FF,  FF,   W_RND(d) + 600);
            add(gru_whh + (size_t)d * F3 * FF,  FF,   W_RND(d) + 1200);
        }
        add(atom_fc_w,      FF,   W_DEC);
        add(bond_fc_w,      2*FF, W_DEC + 39);
        add(bond_fc_w + FF, 2*FF, W_DEC + 49);
        prep_w8<<<(W_TOT + 7) / 8, 256>>>(tab);
    }
    prep_small<<<21, 256>>>(molf, atom_fc_b, bond_fc_b, align_b, attend_b);
    mol_pre_kernel<<<BB, 256>>>(molf, actf);

    #define DUALNONE nullptr, nullptr, 0, nullptr, nullptr

    // molW = molf @ Wm0^T + b
    tgemm8<0><<<tg_grid(BB, FF), 256, TG8_SMEM>>>(
        p_mf8, p_sMF, W_MOL0, mol_al_b, p_molW,
        BB, FF, nullptr, 1, (long)M8PL, DUALNONE);

    for (int t = 0; t < TSTEPS; t++) {
        tgemm8<1><<<tg_grid(BL, FF), 256, TG8_SMEM>>>(
            p_h8, p_sH, W_MOL1, nullptr, p_ctxf,
            BL, FF, p_molW, LL, (long)A8PL, DUALNONE);
        quant_ctx<<<BL / 8, 256>>>();
        tgemm8<0><<<tg_grid(BL, F3, 2), 256, TG8_SMEM>>>(
            p_c8, p_sC, W_MGI, mgru_bih, p_gi,
            BL, F3, nullptr, 1, (long)A8PL,
            p_h8, p_sH, W_MGH, mgru_bhh, p_gh);
        gru8<<<BL / 8, 256>>>(p_gi, p_gh, p_h8, p_sH, 1);
    }

    for (int d = 0; d < RROUNDS; d++) {
        tgemm8<0><<<tg_grid(BL, F3), 256, TG8_SMEM>>>(
            p_a8, p_sA, W_RND(d), p_rb + (size_t)d * F3, p_sst,
            BL, F3, nullptr, 1, (long)A8PL, DUALNONE);
        attn_ctx8<<<BL, 256>>>(p_sst, deg);
        tgemm8<0><<<tg_grid(BL, F3, 2), 256, TG8_SMEM>>>(
            p_c8, p_sC, W_RND(d) + 600, gru_bih + (size_t)d * F3, p_gi,
            BL, F3, nullptr, 1, (long)A8PL,
            p_a8, p_sA, W_RND(d) + 1200, gru_bhh + (size_t)d * F3, p_gh);
        gru8<<<BL / 8, 256>>>(p_gi, p_gh, p_a8, p_sA, 0);
    }

    tgemm8<0><<<tg_grid(BL, 64), 256, TG8_SMEM>>>(
        p_a8, p_sA, W_DEC, p_decb, p_dec,
        BL, 64, nullptr, 1, (long)A8PL, DUALNONE);

    atom_act_kernel<<<(BL + 255) / 256, 256>>>(p_dec, out, BL);
    bond_act_kernel<<<(BL * NNB + 255) / 256, 256>>>(p_dec, deg,
                                                     out + (size_t)BL * 39, BL * NNB);
}

// round 14
// speedup vs baseline: 2.8923x; 2.8923x over previous
#include <cuda_runtime.h>
#include <cuda_bf16.h>
#include <math.h>
#include <stdint.h>

#define BB 128
#define LL 256
#define NNB 8
#define FF 200
#define F3 600
#define BL (BB*LL)
#define RROUNDS 2
#define TSTEPS 2
#define KPAD 224
#define NCH 7

__device__ float g_molW[BB*FF];
__device__ float g_sst[BL*F3];
__device__ float g_gi[BL*F3];
__device__ float g_gh[BL*F3];
__device__ float g_dec[BL*64];
__device__ float g_decb[64];
__device__ float g_rb[RROUNDS*F3];

#define APLANE ((size_t)BL*KPAD)
#define MPLANE ((size_t)BB*KPAD)
__device__ __align__(16) __nv_bfloat16 g_hsp[2*BL*KPAD];
__device__ __align__(16) __nv_bfloat16 g_asp[2*BL*KPAD];
__device__ __align__(16) __nv_bfloat16 g_csp[2*BL*KPAD];
__device__ __align__(16) __nv_bfloat16 g_mfsp[2*BB*KPAD];

#define WROWS 5264
#define WPLANE ((size_t)WROWS*KPAD)
__device__ __align__(16) __nv_bfloat16 g_wsp[2*WROWS*KPAD];

#define W_MOL0 0
#define W_MOL1 200
#define W_MGI  400
#define W_MGH  1000
#define W_RND(d) (1600 + (d)*1800)
#define W_DEC  5200
#define NSEG 14

__device__ __forceinline__ uint32_t smem_u32(const void* p) {
    uint32_t a;
    asm("{ .reg .u64 t; cvta.to.shared.u64 t, %1; cvt.u32.u64 %0, t; }"
        : "=r"(a) : "l"(p));
    return a;
}
__device__ __forceinline__ void ldsm4(uint32_t* r, uint32_t a) {
    asm volatile("ldmatrix.sync.aligned.m8n8.x4.shared.b16 {%0,%1,%2,%3}, [%4];"
        : "=r"(r[0]), "=r"(r[1]), "=r"(r[2]), "=r"(r[3]) : "r"(a));
}
__device__ __forceinline__ void mma_bf16(float* c, const uint32_t* a, const uint32_t* b) {
    asm volatile("mma.sync.aligned.m16n8k16.row.col.f32.bf16.bf16.f32 "
        "{%0,%1,%2,%3}, {%4,%5,%6,%7}, {%8,%9}, {%0,%1,%2,%3};"
        : "+f"(c[0]), "+f"(c[1]), "+f"(c[2]), "+f"(c[3])
        : "r"(a[0]), "r"(a[1]), "r"(a[2]), "r"(a[3]), "r"(b[0]), "r"(b[1]));
}
__device__ __forceinline__ void cpa16(uint32_t dst, const void* src, int srcSize) {
    asm volatile("cp.async.cg.shared.global [%0], [%1], 16, %2;"
        :: "r"(dst), "l"(src), "r"(srcSize));
}
__device__ __forceinline__ void cp_commit() {
    asm volatile("cp.async.commit_group;" ::: "memory");
}
__device__ __forceinline__ void cp_wait0() {
    asm volatile("cp.async.wait_group 0;" ::: "memory");
}
__device__ __forceinline__ void split2(float v, __nv_bfloat16* hi, __nv_bfloat16* lo) {
    __nv_bfloat16 h = __float2bfloat16(v);
    *hi = h;
    *lo = __float2bfloat16(v - __bfloat162float(h));
}

// ---- fused weight prep: 14 segments covering rows [0, W_DEC) ----
struct PrepSeg { const float* src; int stride; int dst; int pad; };
struct PrepTab { PrepSeg s[NSEG]; };

__global__ void prep_all(PrepTab tab)
{
    int idx = blockIdx.x * blockDim.x + threadIdx.x;
    if (idx >= W_DEC * KPAD) return;
    int r = idx / KPAD, k = idx - r * KPAD;
    int si = 0;
    #pragma unroll
    for (int i = 1; i < NSEG; i++) if (r >= tab.s[i].dst) si = i;
    const PrepSeg sg = tab.s[si];
    int lr = r - sg.dst;
    float x = (k < FF) ? sg.src[(size_t)lr * sg.stride + k] : 0.f;
    split2(x, &g_wsp[(size_t)r * KPAD + k], &g_wsp[WPLANE + (size_t)r * KPAD + k]);
}

// ---- fused: mol_pre (blocks 0..127) + all remaining prep (blocks 128+) ----
#define REST_DEC (59*KPAD)
#define REST_MISC (64 + RROUNDS*F3)
#define REST_MOLF (BB*KPAD)
#define REST_TOT (REST_DEC + REST_MISC + REST_MOLF)
#define FUSE_BLKS (BB + (REST_TOT + 255) / 256)

__global__ __launch_bounds__(256) void prep_rest_molpre(
    const float* __restrict__ afw, const float* __restrict__ bfw,
    const float* __restrict__ ab,  const float* __restrict__ bb,
    const float* __restrict__ align_b, const float* __restrict__ attend_b,
    const float* __restrict__ molf, const float* __restrict__ actf)
{
    if (blockIdx.x < BB) {
        // ---- mol_pre: per-batch softmax weight + h0 split ----
        int b = blockIdx.x;
        int tid = threadIdx.x;
        __shared__ float dots[LL];
        __shared__ float red[16];
        const float* mf = molf + (size_t)b * FF;
        int lane = tid & 31, warp = tid >> 5;

        for (int l = warp; l < LL; l += 8) {
            const float* af = actf + ((size_t)b * LL + l) * FF;
            float s = 0.f;
            for (int f = lane; f < FF; f += 32) s += mf[f] * af[f];
            #pragma unroll
            for (int o = 16; o > 0; o >>= 1) s += __shfl_xor_sync(0xffffffffu, s, o);
            if (lane == 0) dots[l] = s;
        }
        __syncthreads();

        float v = dots[tid];
        float m = v;
        #pragma unroll
        for (int o = 16; o > 0; o >>= 1) m = fmaxf(m, __shfl_xor_sync(0xffffffffu, m, o));
        if (lane == 0) red[warp] = m;
        __syncthreads();
        float mx = red[0];
        #pragma unroll
        for (int i = 1; i < 8; i++) mx = fmaxf(mx, red[i]);
        float e = expf(v - mx);
        float s = e;
        #pragma unroll
        for (int o = 16; o > 0; o >>= 1) s += __shfl_xor_sync(0xffffffffu, s, o);
        if (lane == 0) red[8 + warp] = s;
        __syncthreads();
        float tot = 0.f;
        #pragma unroll
        for (int i = 0; i < 8; i++) tot += red[8 + i];
        __syncthreads();
        dots[tid] = e / tot;
        __syncthreads();

        size_t base = (size_t)b * LL * FF;
        for (int i = tid; i < LL * FF; i += 256) {
            int l = i / FF, f = i - l * FF;
            float v2 = dots[l] * mf[f] + actf[base + i];
            size_t si = ((size_t)b * LL + l) * KPAD + f;
            split2(v2, &g_hsp[si], &g_hsp[APLANE + si]);
        }
        return;
    }

    int idx = (blockIdx.x - BB) * 256 + threadIdx.x;
    if (idx < REST_DEC) {
        int r = idx / KPAD, k = idx - r * KPAD;
        float x = 0.f;
        if (k < FF) {
            if (r < 39)      x = afw[(size_t)r * FF + k];
            else if (r < 49) x = bfw[(size_t)(r - 39) * (2 * FF) + k];
            else             x = bfw[(size_t)(r - 49) * (2 * FF) + FF + k];
        }
        size_t rr = (size_t)(W_DEC + r) * KPAD + k;
        split2(x, &g_wsp[rr], &g_wsp[WPLANE + rr]);
        return;
    }
    idx -= REST_DEC;
    if (idx < REST_MISC) {
        if (idx < 64) {
            float v = 0.f;
            if (idx < 39) v = ab[idx];
            else if (idx < 49) v = bb[idx - 39];
            g_decb[idx] = v;
        } else {
            int j = idx - 64;
            int d = j / F3, f = j - d * F3;
            float v = 0.f;
            if (f < 200) v = align_b[d * FF + f];
            else if (f >= 400) v = attend_b[d * FF + f - 400];
            g_rb[j] = v;
        }
        return;
    }
    idx -= REST_MISC;
    if (idx < REST_MOLF) {
        int r = idx / KPAD, k = idx - r * KPAD;
        float x = (k < FF) ? molf[(size_t)r * FF + k] : 0.f;
        split2(x, &g_mfsp[idx], &g_mfsp[MPLANE + idx]);
    }
}

// ---- split-bf16 tensor GEMM (3-pass), optional dual problem via blockIdx.z ----
#define PITCH 80
#define REG 10240
#define STG 40960
#define TG_SMEM (2*STG)

template<int ACT, int OUT>
__global__ __launch_bounds__(256, 2) void tgemm(
    const __nv_bfloat16* __restrict__ Ap0, const __nv_bfloat16* __restrict__ Wp0,
    const float* __restrict__ bias0, float* __restrict__ C0,
    __nv_bfloat16* __restrict__ Cp,
    int M, int Nn, const float* __restrict__ rowAdd, int rpg,
    long aOffB, long wOffB, long cOffE,
    const __nv_bfloat16* Ap1, const __nv_bfloat16* Wp1,
    const float* bias1, float* C1)
{
    extern __shared__ __align__(16) char sm[];
    const uint32_t sb = smem_u32(sm);
    const int tid = threadIdx.x, lane = tid & 31, wid = tid >> 5;
    const int bm = blockIdx.y * 128, bn = blockIdx.x * 128;
    const int wm = (wid & 3) * 32, wn = (wid >> 2) * 64;

    const __nv_bfloat16* Ap = Ap0;
    const __nv_bfloat16* Wp = Wp0;
    const float* bias = bias0;
    float* C = C0;
    if (blockIdx.z == 1) { Ap = Ap1; Wp = Wp1; bias = bias1; C = C1; }

    float acc[2][8][4];
    #pragma unroll
    for (int i = 0; i < 2; i++)
        #pragma unroll
        for (int j = 0; j < 8; j++)
            #pragma unroll
            for (int k = 0; k < 4; k++) acc[i][j][k] = 0.f;

    const int r0 = tid >> 2, q0 = (tid & 3) * 16;
    const int r1 = r0 + 64;
    const int n0 = bn + r0, n1 = bn + r1;
    const int v0 = (n0 < Nn) ? 16 : 0, v1 = (n1 < Nn) ? 16 : 0;
    const char* pA0 = (const char*)(Ap + (size_t)(bm + r0) * KPAD) + q0;
    const char* pA1 = (const char*)(Ap + (size_t)(bm + r1) * KPAD) + q0;
    const char* pB0 = (const char*)(Wp + (size_t)(v0 ? n0 : 0) * KPAD) + q0;
    const char* pB1 = (const char*)(Wp + (size_t)(v1 ? n1 : 0) * KPAD) + q0;
    const uint32_t d0 = (uint32_t)(r0 * PITCH) + q0;
    const uint32_t d1 = (uint32_t)(r1 * PITCH) + q0;

    auto stage_load = [&](int t, int st) {
        const int kb = t * 64;
        const uint32_t s = sb + st * STG;
        cpa16(s + d0,         pA0 + kb, 16);
        cpa16(s + d1,         pA1 + kb, 16);
        cpa16(s + REG + d0,   pA0 + aOffB + kb, 16);
        cpa16(s + REG + d1,   pA1 + aOffB + kb, 16);
        cpa16(s + 2*REG + d0, pB0 + kb, v0);
        cpa16(s + 2*REG + d1, pB1 + kb, v1);
        cpa16(s + 3*REG + d0, pB0 + wOffB + kb, v0);
        cpa16(s + 3*REG + d1, pB1 + wOffB + kb, v1);
    };

    stage_load(0, 0);
    cp_commit();

    const int arow = lane & 15;
    const int brow = lane & 7, sel = lane >> 3;
    const int nOff = (sel >> 1) * 8, kOff = (sel & 1) * 8;

    for (int t = 0; t < NCH; t++) {
        cp_wait0();
        __syncthreads();
        if (t + 1 < NCH) { stage_load(t + 1, (t + 1) & 1); cp_commit(); }
        const uint32_t s = sb + (t & 1) * STG;

        #pragma unroll
        for (int ks = 0; ks < 32; ks += 16) {
            uint32_t ah[2][4], al[2][4];
            const uint32_t akc = (uint32_t)(ks + ((lane >> 4) << 3)) * 2;
            #pragma unroll
            for (int mi = 0; mi < 2; mi++) {
                uint32_t ad = s + (uint32_t)(wm + mi * 16 + arow) * PITCH + akc;
                ldsm4(ah[mi], ad);
                ldsm4(al[mi], ad + REG);
            }
            #pragma unroll
            for (int half = 0; half < 2; half++) {
                uint32_t bh[2][4], blo[2][4];
                #pragma unroll
                for (int p = 0; p < 2; p++) {
                    uint32_t bd = s + 2*REG
                        + (uint32_t)(wn + (half * 2 + p) * 16 + nOff + brow) * PITCH
                        + (uint32_t)(ks + kOff) * 2;
                    ldsm4(bh[p], bd);
                    ldsm4(blo[p], bd + REG);
                }
                #pragma unroll
                for (int mi = 0; mi < 2; mi++)
                    #pragma unroll
                    for (int nj = 0; nj < 4; nj++) {
                        const uint32_t* b2h = &bh[nj >> 1][(nj & 1) * 2];
                        const uint32_t* b2l = &blo[nj >> 1][(nj & 1) * 2];
                        float* a = acc[mi][half * 4 + nj];
                        mma_bf16(a, ah[mi], b2h);
                        mma_bf16(a, ah[mi], b2l);
                        mma_bf16(a, al[mi], b2h);
                    }
            }
        }
        if (t + 1 < NCH) __syncthreads();
    }

    const int lr = lane >> 2, lc = (lane & 3) * 2;
    #pragma unroll
    for (int mi = 0; mi < 2; mi++) {
        #pragma unroll
        for (int hh = 0; hh < 2; hh++) {
            int m = bm + wm + mi * 16 + hh * 8 + lr;
            const float* ra = rowAdd ? (rowAdd + (size_t)(m / rpg) * Nn) : nullptr;
            #pragma unroll
            for (int ni = 0; ni < 8; ni++) {
                int n = bn + wn + ni * 8 + lc;
                if (n >= Nn) continue;
                float v0f = acc[mi][ni][hh * 2 + 0];
                float v1f = acc[mi][ni][hh * 2 + 1];
                if (bias) { v0f += bias[n]; v1f += bias[n + 1]; }
                if (ra)   { v0f += ra[n];   v1f += ra[n + 1]; }
                if (ACT == 1) { v0f = (v0f > 0.f) ? v0f : expm1f(v0f);
                                v1f = (v1f > 0.f) ? v1f : expm1f(v1f); }
                else if (ACT == 2) { v0f = fmaxf(v0f, 0.f); v1f = fmaxf(v1f, 0.f); }
                if (OUT == 0) {
                    *(float2*)&C[(size_t)m * Nn + n] = make_float2(v0f, v1f);
                } else {
                    __nv_bfloat162 h2 = __floats2bfloat162_rn(v0f, v1f);
                    __nv_bfloat162 l2 = __floats2bfloat162_rn(
                        v0f - __bfloat162float(h2.x), v1f - __bfloat162float(h2.y));
                    size_t ci = (size_t)m * KPAD + n;
                    *(__nv_bfloat162*)&Cp[ci] = h2;
                    *(__nv_bfloat162*)&Cp[cOffE + ci] = l2;
                }
            }
        }
    }
}

__global__ __launch_bounds__(256) void gru_combine_kernel(
    const float* __restrict__ gi, const float* __restrict__ gh,
    const __nv_bfloat16* __restrict__ hsp, int writeH, int total)
{
    int idx = blockIdx.x * blockDim.x + threadIdx.x;
    if (idx >= total) return;
    int m = idx / FF, f = idx - m * FF;
    size_t b3 = (size_t)m * F3;
    float ir = gi[b3 + f], iz = gi[b3 + FF + f], in_ = gi[b3 + 2 * FF + f];
    float hr = gh[b3 + f], hz = gh[b3 + FF + f], hn = gh[b3 + 2 * FF + f];
    float r = 1.f / (1.f + expf(-(ir + hr)));
    float z = 1.f / (1.f + expf(-(iz + hz)));
    float n = tanhf(in_ + r * hn);
    size_t si = (size_t)m * KPAD + f;
    float h = __bfloat162float(hsp[si]) + __bfloat162float(hsp[APLANE + si]);
    float o = (1.f - z) * n + z * h;
    if (writeH) split2(o, &g_hsp[si], &g_hsp[APLANE + si]);
    float a = fmaxf(o, 0.f);
    split2(a, &g_asp[si], &g_asp[APLANE + si]);
}

__global__ __launch_bounds__(256) void attn_ctx_kernel(
    const float* __restrict__ sst, const int* __restrict__ deg)
{
    int bl = blockIdx.x;
    int b = bl >> 8;
    int tid = threadIdx.x;
    __shared__ int sidx[NNB];
    if (tid < NNB) sidx[tid] = deg[(size_t)bl * NNB + tid];
    __syncthreads();
    if (tid >= FF) return;
    int f = tid;
    float s1v = sst[(size_t)bl * F3 + f];
    float sc[NNB];
    float mx = -3.4e38f;
    #pragma unroll
    for (int n = 0; n < NNB; n++) {
        int j = sidx[n];
        float v = s1v + sst[((size_t)b * LL + j) * F3 + 200 + f];
        v = (v >= 0.f) ? v : 0.01f * v;
        if (j == LL - 1) v += -9e8f;
        sc[n] = v;
        mx = fmaxf(mx, v);
    }
    float sum = 0.f;
    #pragma unroll
    for (int n = 0; n < NNB; n++) { sc[n] = expf(sc[n] - mx); sum += sc[n]; }
    float inv = 1.f / sum;
    float c = 0.f;
    #pragma unroll
    for (int n = 0; n < NNB; n++) {
        int j = sidx[n];
        if (j != LL - 1)
            c += sc[n] * inv * sst[((size_t)b * LL + j) * F3 + 400 + f];
    }
    c = (c > 0.f) ? c : expm1f(c);
    size_t si = (size_t)bl * KPAD + f;
    split2(c, &g_csp[si], &g_csp[APLANE + si]);
}

__device__ __forceinline__ void seg_softmax_acc(const float* v, float* y, int lo, int hi) {
    float m = -3.4e38f;
    for (int i = lo; i < hi; i++) m = fmaxf(m, v[i]);
    float s = 0.f;
    for (int i = lo; i < hi; i++) s += expf(v[i] - m);
    float inv = 1.f / s;
    for (int i = lo; i < hi; i++) y[i] += expf(v[i] - m) * inv;
}
__device__ __forceinline__ float sigf(float x) { return 1.f / (1.f + expf(-x)); }

__global__ __launch_bounds__(256) void atom_act_kernel(
    const float* __restrict__ dec, float* __restrict__ out, int rows)
{
    int m = blockIdx.x * blockDim.x + threadIdx.x;
    if (m >= rows) return;
    const float* x = dec + (size_t)m * 64;
    float v[39], y[39];
    #pragma unroll
    for (int i = 0; i < 39; i++) { v[i] = x[i]; y[i] = 0.f; }
    seg_softmax_acc(v, y, 0, 16);
    seg_softmax_acc(v, y, 16, 22);
    seg_softmax_acc(v, y, 24, 30);
    seg_softmax_acc(v, y, 31, 36);
    y[24] += fmaxf(v[24], 0.f);
    y[30] += sigf(v[30]);
    y[36] += sigf(v[36]);
    y[37] += sigf(v[37]);
    y[38] += sigf(v[38]);
    float* o = out + (size_t)m * 39;
    #pragma unroll
    for (int i = 0; i < 39; i++) o[i] = y[i];
}

__global__ __launch_bounds__(256) void bond_act_kernel(
    const float* __restrict__ dec, const int* __restrict__ deg,
    float* __restrict__ out, int total)
{
    int id = blockIdx.x * blockDim.x + threadIdx.x;
    if (id >= total) return;
    int bl = id / NNB;
    int b = bl >> 8;
    int j = deg[id];
    const float* a = dec + (size_t)bl * 64 + 39;
    const float* c = dec + ((size_t)b * LL + j) * 64 + 49;
    float v[10], y[10];
    #pragma unroll
    for (int k = 0; k < 10; k++) { v[k] = a[k] + c[k]; y[k] = 0.f; }
    seg_softmax_acc(v, y, 0, 4);
    seg_softmax_acc(v, y, 6, 10);
    y[4] += sigf(v[4]);
    y[5] += sigf(v[5]);
    float* o = out + (size_t)id * 10;
    #pragma unroll
    for (int k = 0; k < 10; k++) o[k] = y[k];
}

static inline dim3 tg_grid(int M, int N, int z = 1) {
    return dim3((N + 127) / 128, M / 128, z);
}

extern "C" void kernel_launch(void* const* d_in, const int* in_sizes, int n_in,
                              void* d_out, int out_size)
{
    const int*   deg        = (const int*)  d_in[2];
    const float* molf       = (const float*)d_in[5];
    const float* actf       = (const float*)d_in[6];
    const float* atom_fc_w  = (const float*)d_in[7];
    const float* atom_fc_b  = (const float*)d_in[8];
    const float* bond_fc_w  = (const float*)d_in[9];
    const float* bond_fc_b  = (const float*)d_in[10];
    const float* align_w    = (const float*)d_in[11];
    const float* align_b    = (const float*)d_in[12];
    const float* attend_w   = (const float*)d_in[13];
    const float* attend_b   = (const float*)d_in[14];
    const float* gru_wih    = (const float*)d_in[15];
    const float* gru_whh    = (const float*)d_in[16];
    const float* gru_bih    = (const float*)d_in[17];
    const float* gru_bhh    = (const float*)d_in[18];
    const float* mol_al_w   = (const float*)d_in[19];
    const float* mol_al_b   = (const float*)d_in[20];
    const float* mgru_wih   = (const float*)d_in[21];
    const float* mgru_whh   = (const float*)d_in[22];
    const float* mgru_bih   = (const float*)d_in[23];
    const float* mgru_bhh   = (const float*)d_in[24];
    float* out = (float*)d_out;

    float *p_molW, *p_sst, *p_gi, *p_gh, *p_dec, *p_decb, *p_rb;
    __nv_bfloat16 *p_w, *p_h, *p_a, *p_c, *p_mf;
    cudaGetSymbolAddress((void**)&p_molW, g_molW);
    cudaGetSymbolAddress((void**)&p_sst,  g_sst);
    cudaGetSymbolAddress((void**)&p_gi,   g_gi);
    cudaGetSymbolAddress((void**)&p_gh,   g_gh);
    cudaGetSymbolAddress((void**)&p_dec,  g_dec);
    cudaGetSymbolAddress((void**)&p_decb, g_decb);
    cudaGetSymbolAddress((void**)&p_rb,   g_rb);
    cudaGetSymbolAddress((void**)&p_w,    g_wsp);
    cudaGetSymbolAddress((void**)&p_h,    g_hsp);
    cudaGetSymbolAddress((void**)&p_a,    g_asp);
    cudaGetSymbolAddress((void**)&p_c,    g_csp);
    cudaGetSymbolAddress((void**)&p_mf,   g_mfsp);

    cudaFuncSetAttribute(tgemm<0,0>, cudaFuncAttributeMaxDynamicSharedMemorySize, TG_SMEM);
    cudaFuncSetAttribute(tgemm<1,1>, cudaFuncAttributeMaxDynamicSharedMemorySize, TG_SMEM);

    const long AOB = (long)(APLANE * 2);
    const long MOB = (long)(MPLANE * 2);
    const long WOB = (long)(WPLANE * 2);

    // launch 0: bulk weight prep
    {
        PrepTab tab;
        int i = 0;
        auto add = [&](const float* s, int st, int dst) {
            tab.s[i].src = s; tab.s[i].stride = st; tab.s[i].dst = dst; tab.s[i].pad = 0; i++;
        };
        add(mol_al_w,      2*FF, W_MOL0);
        add(mol_al_w + FF, 2*FF, W_MOL1);
        add(mgru_wih,      FF,   W_MGI);
        add(mgru_whh,      FF,   W_MGH);
        for (int d = 0; d < RROUNDS; d++) {
            const float* aw = align_w + (size_t)d * FF * 2 * FF;
            add(aw,                             2*FF, W_RND(d) + 0);
            add(aw + FF,                        2*FF, W_RND(d) + 200);
            add(attend_w + (size_t)d * FF * FF, FF,   W_RND(d) + 400);
            add(gru_wih + (size_t)d * F3 * FF,  FF,   W_RND(d) + 600);
            add(gru_whh + (size_t)d * F3 * FF,  FF,   W_RND(d) + 1200);
        }
        prep_all<<<(W_DEC * KPAD + 255) / 256, 256>>>(tab);
    }
    // launch 1: fused mol_pre + remaining prep
    prep_rest_molpre<<<FUSE_BLKS, 256>>>(atom_fc_w, bond_fc_w,
                                         atom_fc_b, bond_fc_b,
                                         align_b, attend_b, molf, actf);

    #define WOFFP(o) (p_w + (size_t)(o) * KPAD)
    #define NODUAL nullptr, nullptr, nullptr, nullptr

    // launch 2: molW (tiny)
    tgemm<0,0><<<tg_grid(BB, FF), 256, TG_SMEM>>>(
        p_mf, WOFFP(W_MOL0), mol_al_b, p_molW, nullptr,
        BB, FF, nullptr, 1, MOB, WOB, 0, NODUAL);

    for (int t = 0; t < TSTEPS; t++) {
        // launch 3 (first iter): ctx GEMM (grid 2x256) — profiler target if idx3
        tgemm<1,1><<<tg_grid(BL, FF), 256, TG_SMEM>>>(
            p_h, WOFFP(W_MOL1), nullptr, nullptr, p_c,
            BL, FF, p_molW, LL, AOB, WOB, (long)APLANE, NODUAL);
        // launch 4 (first iter): dual gi+gh (grid 5x256x2)
        tgemm<0,0><<<tg_grid(BL, F3, 2), 256, TG_SMEM>>>(
            p_c, WOFFP(W_MGI), mgru_bih, p_gi, nullptr,
            BL, F3, nullptr, 1, AOB, WOB, 0,
            p_h, WOFFP(W_MGH), mgru_bhh, p_gh);
        gru_combine_kernel<<<(BL * FF + 255) / 256, 256>>>(p_gi, p_gh, p_h, 1, BL * FF);
    }

    for (int d = 0; d < RROUNDS; d++) {
        tgemm<0,0><<<tg_grid(BL, F3), 256, TG_SMEM>>>(
            p_a, WOFFP(W_RND(d)), p_rb + (size_t)d * F3, p_sst, nullptr,
            BL, F3, nullptr, 1, AOB, WOB, 0, NODUAL);
        attn_ctx_kernel<<<BL, 256>>>(p_sst, deg);
        tgemm<0,0><<<tg_grid(BL, F3, 2), 256, TG_SMEM>>>(
            p_c, WOFFP(W_RND(d) + 600), gru_bih + (size_t)d * F3, p_gi, nullptr,
            BL, F3, nullptr, 1, AOB, WOB, 0,
            p_a, WOFFP(W_RND(d) + 1200), gru_bhh + (size_t)d * F3, p_gh);
        gru_combine_kernel<<<(BL * FF + 255) / 256, 256>>>(p_gi, p_gh, p_a, 0, BL * FF);
    }

    tgemm<0,0><<<tg_grid(BL, 64), 256, TG_SMEM>>>(
        p_a, WOFFP(W_DEC), p_decb, p_dec, nullptr,
        BL, 64, nullptr, 1, AOB, WOB, 0, NODUAL);

    atom_act_kernel<<<(BL + 255) / 256, 256>>>(p_dec, out, BL);
    bond_act_kernel<<<(BL * NNB + 255) / 256, 256>>>(p_dec, deg,
                                                     out + (size_t)BL * 39, BL * NNB);
}

// round 15
// speedup vs baseline: 3.0336x; 1.0489x over previous
#include <cuda_runtime.h>
#include <cuda_bf16.h>
#include <math.h>
#include <stdint.h>

#define BB 128
#define LL 256
#define NNB 8
#define FF 200
#define F3 600
#define BL (BB*LL)
#define RROUNDS 2
#define TSTEPS 2
#define KPAD 224
#define NCH 7

__device__ float g_molW[BB*FF];
__device__ float g_sst[BL*F3];
__device__ float g_gi[BL*F3];
__device__ float g_gh[BL*F3];
__device__ float g_dec[BL*64];
__device__ float g_decb[64];
__device__ float g_rb[RROUNDS*F3];

#define APLANE ((size_t)BL*KPAD)
#define MPLANE ((size_t)BB*KPAD)
__device__ __align__(16) __nv_bfloat16 g_hsp[2*BL*KPAD];
__device__ __align__(16) __nv_bfloat16 g_asp[2*BL*KPAD];
__device__ __align__(16) __nv_bfloat16 g_csp[2*BL*KPAD];
__device__ __align__(16) __nv_bfloat16 g_mfsp[2*BB*KPAD];

#define WROWS 5264
#define WPLANE ((size_t)WROWS*KPAD)
__device__ __align__(16) __nv_bfloat16 g_wsp[2*WROWS*KPAD];

#define W_MOL0 0
#define W_MOL1 200
#define W_MGI  400
#define W_MGH  1000
#define W_RND(d) (1600 + (d)*1800)
#define W_DEC  5200
#define NSEG 14

__device__ __forceinline__ uint32_t smem_u32(const void* p) {
    uint32_t a;
    asm("{ .reg .u64 t; cvta.to.shared.u64 t, %1; cvt.u32.u64 %0, t; }"
        : "=r"(a) : "l"(p));
    return a;
}
__device__ __forceinline__ void ldsm4(uint32_t* r, uint32_t a) {
    asm volatile("ldmatrix.sync.aligned.m8n8.x4.shared.b16 {%0,%1,%2,%3}, [%4];"
        : "=r"(r[0]), "=r"(r[1]), "=r"(r[2]), "=r"(r[3]) : "r"(a));
}
__device__ __forceinline__ void mma_bf16(float* c, const uint32_t* a, const uint32_t* b) {
    asm volatile("mma.sync.aligned.m16n8k16.row.col.f32.bf16.bf16.f32 "
        "{%0,%1,%2,%3}, {%4,%5,%6,%7}, {%8,%9}, {%0,%1,%2,%3};"
        : "+f"(c[0]), "+f"(c[1]), "+f"(c[2]), "+f"(c[3])
        : "r"(a[0]), "r"(a[1]), "r"(a[2]), "r"(a[3]), "r"(b[0]), "r"(b[1]));
}
__device__ __forceinline__ void cpa16(uint32_t dst, const void* src, int srcSize) {
    asm volatile("cp.async.cg.shared.global [%0], [%1], 16, %2;"
        :: "r"(dst), "l"(src), "r"(srcSize));
}
__device__ __forceinline__ void cp_commit() {
    asm volatile("cp.async.commit_group;" ::: "memory");
}
__device__ __forceinline__ void cp_wait1() {
    asm volatile("cp.async.wait_group 1;" ::: "memory");
}
__device__ __forceinline__ void split2(float v, __nv_bfloat16* hi, __nv_bfloat16* lo) {
    __nv_bfloat16 h = __float2bfloat16(v);
    *hi = h;
    *lo = __float2bfloat16(v - __bfloat162float(h));
}
// swizzled byte-offset within a 128x64B region (conflict-free for ldsm octets)
__device__ __forceinline__ uint32_t swz(int row, int kbyte) {
    return (uint32_t)(row * 64) + ((uint32_t)(((kbyte >> 4) ^ ((row >> 1) & 3)) << 4));
}

// ---- fused weight prep ----
struct PrepSeg { const float* src; int stride; int dst; int pad; };
struct PrepTab { PrepSeg s[NSEG]; };

__global__ void prep_all(PrepTab tab)
{
    int idx = blockIdx.x * blockDim.x + threadIdx.x;
    if (idx >= W_DEC * KPAD) return;
    int r = idx / KPAD, k = idx - r * KPAD;
    int si = 0;
    #pragma unroll
    for (int i = 1; i < NSEG; i++) if (r >= tab.s[i].dst) si = i;
    const PrepSeg sg = tab.s[si];
    int lr = r - sg.dst;
    float x = (k < FF) ? sg.src[(size_t)lr * sg.stride + k] : 0.f;
    split2(x, &g_wsp[(size_t)r * KPAD + k], &g_wsp[WPLANE + (size_t)r * KPAD + k]);
}

#define REST_DEC (59*KPAD)
#define REST_MISC (64 + RROUNDS*F3)
#define REST_MOLF (BB*KPAD)
#define REST_TOT (REST_DEC + REST_MISC + REST_MOLF)
#define FUSE_BLKS (BB + (REST_TOT + 255) / 256)

__global__ __launch_bounds__(256) void prep_rest_molpre(
    const float* __restrict__ afw, const float* __restrict__ bfw,
    const float* __restrict__ ab,  const float* __restrict__ bb,
    const float* __restrict__ align_b, const float* __restrict__ attend_b,
    const float* __restrict__ molf, const float* __restrict__ actf)
{
    if (blockIdx.x < BB) {
        int b = blockIdx.x;
        int tid = threadIdx.x;
        __shared__ float dots[LL];
        __shared__ float red[16];
        const float* mf = molf + (size_t)b * FF;
        int lane = tid & 31, warp = tid >> 5;

        for (int l = warp; l < LL; l += 8) {
            const float* af = actf + ((size_t)b * LL + l) * FF;
            float s = 0.f;
            for (int f = lane; f < FF; f += 32) s += mf[f] * af[f];
            #pragma unroll
            for (int o = 16; o > 0; o >>= 1) s += __shfl_xor_sync(0xffffffffu, s, o);
            if (lane == 0) dots[l] = s;
        }
        __syncthreads();

        float v = dots[tid];
        float m = v;
        #pragma unroll
        for (int o = 16; o > 0; o >>= 1) m = fmaxf(m, __shfl_xor_sync(0xffffffffu, m, o));
        if (lane == 0) red[warp] = m;
        __syncthreads();
        float mx = red[0];
        #pragma unroll
        for (int i = 1; i < 8; i++) mx = fmaxf(mx, red[i]);
        float e = expf(v - mx);
        float s = e;
        #pragma unroll
        for (int o = 16; o > 0; o >>= 1) s += __shfl_xor_sync(0xffffffffu, s, o);
        if (lane == 0) red[8 + warp] = s;
        __syncthreads();
        float tot = 0.f;
        #pragma unroll
        for (int i = 0; i < 8; i++) tot += red[8 + i];
        __syncthreads();
        dots[tid] = e / tot;
        __syncthreads();

        size_t base = (size_t)b * LL * FF;
        for (int i = tid; i < LL * FF; i += 256) {
            int l = i / FF, f = i - l * FF;
            float v2 = dots[l] * mf[f] + actf[base + i];
            size_t si = ((size_t)b * LL + l) * KPAD + f;
            split2(v2, &g_hsp[si], &g_hsp[APLANE + si]);
        }
        return;
    }

    int idx = (blockIdx.x - BB) * 256 + threadIdx.x;
    if (idx < REST_DEC) {
        int r = idx / KPAD, k = idx - r * KPAD;
        float x = 0.f;
        if (k < FF) {
            if (r < 39)      x = afw[(size_t)r * FF + k];
            else if (r < 49) x = bfw[(size_t)(r - 39) * (2 * FF) + k];
            else             x = bfw[(size_t)(r - 49) * (2 * FF) + FF + k];
        }
        size_t rr = (size_t)(W_DEC + r) * KPAD + k;
        split2(x, &g_wsp[rr], &g_wsp[WPLANE + rr]);
        return;
    }
    idx -= REST_DEC;
    if (idx < REST_MISC) {
        if (idx < 64) {
            float v = 0.f;
            if (idx < 39) v = ab[idx];
            else if (idx < 49) v = bb[idx - 39];
            g_decb[idx] = v;
        } else {
            int j = idx - 64;
            int d = j / F3, f = j - d * F3;
            float v = 0.f;
            if (f < 200) v = align_b[d * FF + f];
            else if (f >= 400) v = attend_b[d * FF + f - 400];
            g_rb[j] = v;
        }
        return;
    }
    idx -= REST_MISC;
    if (idx < REST_MOLF) {
        int r = idx / KPAD, k = idx - r * KPAD;
        float x = (k < FF) ? molf[(size_t)r * FF + k] : 0.f;
        split2(x, &g_mfsp[idx], &g_mfsp[MPLANE + idx]);
    }
}

// ---- split-bf16 tensor GEMM: 3-stage pipeline, swizzled pitch-64 smem ----
#define REG 8192               // 128 rows * 64 B
#define STG 32768              // 4 regions
#define NSTG 3
#define TG_SMEM (NSTG*STG)     // 98304

template<int ACT, int OUT>
__global__ __launch_bounds__(256, 2) void tgemm(
    const __nv_bfloat16* __restrict__ Ap0, const __nv_bfloat16* __restrict__ Wp0,
    const float* __restrict__ bias0, float* __restrict__ C0,
    __nv_bfloat16* __restrict__ Cp,
    int M, int Nn, const float* __restrict__ rowAdd, int rpg,
    long aOffB, long wOffB, long cOffE,
    const __nv_bfloat16* Ap1, const __nv_bfloat16* Wp1,
    const float* bias1, float* C1)
{
    extern __shared__ __align__(16) char sm[];
    const uint32_t sb = smem_u32(sm);
    const int tid = threadIdx.x, lane = tid & 31, wid = tid >> 5;
    const int bm = blockIdx.y * 128, bn = blockIdx.x * 128;
    const int wm = (wid & 3) * 32, wn = (wid >> 2) * 64;

    const __nv_bfloat16* Ap = Ap0;
    const __nv_bfloat16* Wp = Wp0;
    const float* bias = bias0;
    float* C = C0;
    if (blockIdx.z == 1) { Ap = Ap1; Wp = Wp1; bias = bias1; C = C1; }

    float acc[2][8][4];
    #pragma unroll
    for (int i = 0; i < 2; i++)
        #pragma unroll
        for (int j = 0; j < 8; j++)
            #pragma unroll
            for (int k = 0; k < 4; k++) acc[i][j][k] = 0.f;

    // loader: each thread owns rows r0 and r0+64 at seg s0 (16B each)
    const int r0 = tid >> 2, s0b = (tid & 3) * 16;
    const int r1 = r0 + 64;
    const int n0 = bn + r0, n1 = bn + r1;
    const int v0 = (n0 < Nn) ? 16 : 0, v1 = (n1 < Nn) ? 16 : 0;
    const char* pA0 = (const char*)(Ap + (size_t)(bm + r0) * KPAD) + s0b;
    const char* pA1 = (const char*)(Ap + (size_t)(bm + r1) * KPAD) + s0b;
    const char* pB0 = (const char*)(Wp + (size_t)(v0 ? n0 : 0) * KPAD) + s0b;
    const char* pB1 = (const char*)(Wp + (size_t)(v1 ? n1 : 0) * KPAD) + s0b;
    const uint32_t d0 = swz(r0, s0b);
    const uint32_t d1 = swz(r1, s0b);     // = d0 + 4096 (same xor class)

    auto stage_load = [&](int t, int st) {
        const int kb = t * 64;
        const uint32_t s = sb + st * STG;
        cpa16(s + d0,         pA0 + kb, 16);
        cpa16(s + d1,         pA1 + kb, 16);
        cpa16(s + REG + d0,   pA0 + aOffB + kb, 16);
        cpa16(s + REG + d1,   pA1 + aOffB + kb, 16);
        cpa16(s + 2*REG + d0, pB0 + kb, v0);
        cpa16(s + 2*REG + d1, pB1 + kb, v1);
        cpa16(s + 3*REG + d0, pB0 + wOffB + kb, v0);
        cpa16(s + 3*REG + d1, pB1 + wOffB + kb, v1);
    };

    stage_load(0, 0); cp_commit();
    stage_load(1, 1); cp_commit();

    const int arow = lane & 15;
    const int brow = lane & 7, sel = lane >> 3;
    const int nOff = (sel >> 1) * 8, kOff = (sel & 1) * 8;

    int st = 0;
    for (int t = 0; t < NCH; t++) {
        cp_wait1();
        __syncthreads();
        if (t + 2 < NCH) stage_load(t + 2, (st + 2) % NSTG);
        cp_commit();
        const uint32_t s = sb + st * STG;

        #pragma unroll
        for (int ks = 0; ks < 32; ks += 16) {
            uint32_t ah[2][4], al[2][4];
            const int akc = (ks + ((lane >> 4) << 3)) * 2;   // 0,16,32,48
            #pragma unroll
            for (int mi = 0; mi < 2; mi++) {
                int rowA = wm + mi * 16 + arow;
                uint32_t ad = s + swz(rowA, akc);
                ldsm4(ah[mi], ad);
                ldsm4(al[mi], ad + REG);
            }
            #pragma unroll
            for (int half = 0; half < 2; half++) {
                uint32_t bh[2][4], blo[2][4];
                #pragma unroll
                for (int p = 0; p < 2; p++) {
                    int rowB = wn + (half * 2 + p) * 16 + nOff + brow;
                    uint32_t bd = s + 2*REG + swz(rowB, (ks + kOff) * 2);
                    ldsm4(bh[p], bd);
                    ldsm4(blo[p], bd + REG);
                }
                #pragma unroll
                for (int mi = 0; mi < 2; mi++)
                    #pragma unroll
                    for (int nj = 0; nj < 4; nj++) {
                        const uint32_t* b2h = &bh[nj >> 1][(nj & 1) * 2];
                        const uint32_t* b2l = &blo[nj >> 1][(nj & 1) * 2];
                        float* a = acc[mi][half * 4 + nj];
                        mma_bf16(a, ah[mi], b2h);
                        mma_bf16(a, ah[mi], b2l);
                        mma_bf16(a, al[mi], b2h);
                    }
            }
        }
        st = (st + 1) % NSTG;
    }

    const int lr = lane >> 2, lc = (lane & 3) * 2;
    #pragma unroll
    for (int mi = 0; mi < 2; mi++) {
        #pragma unroll
        for (int hh = 0; hh < 2; hh++) {
            int m = bm + wm + mi * 16 + hh * 8 + lr;
            const float* ra = rowAdd ? (rowAdd + (size_t)(m / rpg) * Nn) : nullptr;
            #pragma unroll
            for (int ni = 0; ni < 8; ni++) {
                int n = bn + wn + ni * 8 + lc;
                if (n >= Nn) continue;
                float v0f = acc[mi][ni][hh * 2 + 0];
                float v1f = acc[mi][ni][hh * 2 + 1];
                if (bias) { v0f += bias[n]; v1f += bias[n + 1]; }
                if (ra)   { v0f += ra[n];   v1f += ra[n + 1]; }
                if (ACT == 1) { v0f = (v0f > 0.f) ? v0f : expm1f(v0f);
                                v1f = (v1f > 0.f) ? v1f : expm1f(v1f); }
                else if (ACT == 2) { v0f = fmaxf(v0f, 0.f); v1f = fmaxf(v1f, 0.f); }
                if (OUT == 0) {
                    *(float2*)&C[(size_t)m * Nn + n] = make_float2(v0f, v1f);
                } else {
                    __nv_bfloat162 h2 = __floats2bfloat162_rn(v0f, v1f);
                    __nv_bfloat162 l2 = __floats2bfloat162_rn(
                        v0f - __bfloat162float(h2.x), v1f - __bfloat162float(h2.y));
                    size_t ci = (size_t)m * KPAD + n;
                    *(__nv_bfloat162*)&Cp[ci] = h2;
                    *(__nv_bfloat162*)&Cp[cOffE + ci] = l2;
                }
            }
        }
    }
}

__global__ __launch_bounds__(256) void gru_combine_kernel(
    const float* __restrict__ gi, const float* __restrict__ gh,
    const __nv_bfloat16* __restrict__ hsp, int writeH, int total)
{
    int idx = blockIdx.x * blockDim.x + threadIdx.x;
    if (idx >= total) return;
    int m = idx / FF, f = idx - m * FF;
    size_t b3 = (size_t)m * F3;
    float ir = gi[b3 + f], iz = gi[b3 + FF + f], in_ = gi[b3 + 2 * FF + f];
    float hr = gh[b3 + f], hz = gh[b3 + FF + f], hn = gh[b3 + 2 * FF + f];
    float r = 1.f / (1.f + expf(-(ir + hr)));
    float z = 1.f / (1.f + expf(-(iz + hz)));
    float n = tanhf(in_ + r * hn);
    size_t si = (size_t)m * KPAD + f;
    float h = __bfloat162float(hsp[si]) + __bfloat162float(hsp[APLANE + si]);
    float o = (1.f - z) * n + z * h;
    if (writeH) split2(o, &g_hsp[si], &g_hsp[APLANE + si]);
    float a = fmaxf(o, 0.f);
    split2(a, &g_asp[si], &g_asp[APLANE + si]);
}

__global__ __launch_bounds__(256) void attn_ctx_kernel(
    const float* __restrict__ sst, const int* __restrict__ deg)
{
    int bl = blockIdx.x;
    int b = bl >> 8;
    int tid = threadIdx.x;
    __shared__ int sidx[NNB];
    if (tid < NNB) sidx[tid] = deg[(size_t)bl * NNB + tid];
    __syncthreads();
    if (tid >= FF) return;
    int f = tid;
    float s1v = sst[(size_t)bl * F3 + f];
    float sc[NNB];
    float mx = -3.4e38f;
    #pragma unroll
    for (int n = 0; n < NNB; n++) {
        int j = sidx[n];
        float v = s1v + sst[((size_t)b * LL + j) * F3 + 200 + f];
        v = (v >= 0.f) ? v : 0.01f * v;
        if (j == LL - 1) v += -9e8f;
        sc[n] = v;
        mx = fmaxf(mx, v);
    }
    float sum = 0.f;
    #pragma unroll
    for (int n = 0; n < NNB; n++) { sc[n] = expf(sc[n] - mx); sum += sc[n]; }
    float inv = 1.f / sum;
    float c = 0.f;
    #pragma unroll
    for (int n = 0; n < NNB; n++) {
        int j = sidx[n];
        if (j != LL - 1)
            c += sc[n] * inv * sst[((size_t)b * LL + j) * F3 + 400 + f];
    }
    c = (c > 0.f) ? c : expm1f(c);
    size_t si = (size_t)bl * KPAD + f;
    split2(c, &g_csp[si], &g_csp[APLANE + si]);
}

__device__ __forceinline__ void seg_softmax_acc(const float* v, float* y, int lo, int hi) {
    float m = -3.4e38f;
    for (int i = lo; i < hi; i++) m = fmaxf(m, v[i]);
    float s = 0.f;
    for (int i = lo; i < hi; i++) s += expf(v[i] - m);
    float inv = 1.f / s;
    for (int i = lo; i < hi; i++) y[i] += expf(v[i] - m) * inv;
}
__device__ __forceinline__ float sigf(float x) { return 1.f / (1.f + expf(-x)); }

__global__ __launch_bounds__(256) void atom_act_kernel(
    const float* __restrict__ dec, float* __restrict__ out, int rows)
{
    int m = blockIdx.x * blockDim.x + threadIdx.x;
    if (m >= rows) return;
    const float* x = dec + (size_t)m * 64;
    float v[39], y[39];
    #pragma unroll
    for (int i = 0; i < 39; i++) { v[i] = x[i]; y[i] = 0.f; }
    seg_softmax_acc(v, y, 0, 16);
    seg_softmax_acc(v, y, 16, 22);
    seg_softmax_acc(v, y, 24, 30);
    seg_softmax_acc(v, y, 31, 36);
    y[24] += fmaxf(v[24], 0.f);
    y[30] += sigf(v[30]);
    y[36] += sigf(v[36]);
    y[37] += sigf(v[37]);
    y[38] += sigf(v[38]);
    float* o = out + (size_t)m * 39;
    #pragma unroll
    for (int i = 0; i < 39; i++) o[i] = y[i];
}

__global__ __launch_bounds__(256) void bond_act_kernel(
    const float* __restrict__ dec, const int* __restrict__ deg,
    float* __restrict__ out, int total)
{
    int id = blockIdx.x * blockDim.x + threadIdx.x;
    if (id >= total) return;
    int bl = id / NNB;
    int b = bl >> 8;
    int j = deg[id];
    const float* a = dec + (size_t)bl * 64 + 39;
    const float* c = dec + ((size_t)b * LL + j) * 64 + 49;
    float v[10], y[10];
    #pragma unroll
    for (int k = 0; k < 10; k++) { v[k] = a[k] + c[k]; y[k] = 0.f; }
    seg_softmax_acc(v, y, 0, 4);
    seg_softmax_acc(v, y, 6, 10);
    y[4] += sigf(v[4]);
    y[5] += sigf(v[5]);
    float* o = out + (size_t)id * 10;
    #pragma unroll
    for (int k = 0; k < 10; k++) o[k] = y[k];
}

static inline dim3 tg_grid(int M, int N, int z = 1) {
    return dim3((N + 127) / 128, M / 128, z);
}

extern "C" void kernel_launch(void* const* d_in, const int* in_sizes, int n_in,
                              void* d_out, int out_size)
{
    const int*   deg        = (const int*)  d_in[2];
    const float* molf       = (const float*)d_in[5];
    const float* actf       = (const float*)d_in[6];
    const float* atom_fc_w  = (const float*)d_in[7];
    const float* atom_fc_b  = (const float*)d_in[8];
    const float* bond_fc_w  = (const float*)d_in[9];
    const float* bond_fc_b  = (const float*)d_in[10];
    const float* align_w    = (const float*)d_in[11];
    const float* align_b    = (const float*)d_in[12];
    const float* attend_w   = (const float*)d_in[13];
    const float* attend_b   = (const float*)d_in[14];
    const float* gru_wih    = (const float*)d_in[15];
    const float* gru_whh    = (const float*)d_in[16];
    const float* gru_bih    = (const float*)d_in[17];
    const float* gru_bhh    = (const float*)d_in[18];
    const float* mol_al_w   = (const float*)d_in[19];
    const float* mol_al_b   = (const float*)d_in[20];
    const float* mgru_wih   = (const float*)d_in[21];
    const float* mgru_whh   = (const float*)d_in[22];
    const float* mgru_bih   = (const float*)d_in[23];
    const float* mgru_bhh   = (const float*)d_in[24];
    float* out = (float*)d_out;

    float *p_molW, *p_sst, *p_gi, *p_gh, *p_dec, *p_decb, *p_rb;
    __nv_bfloat16 *p_w, *p_h, *p_a, *p_c, *p_mf;
    cudaGetSymbolAddress((void**)&p_molW, g_molW);
    cudaGetSymbolAddress((void**)&p_sst,  g_sst);
    cudaGetSymbolAddress((void**)&p_gi,   g_gi);
    cudaGetSymbolAddress((void**)&p_gh,   g_gh);
    cudaGetSymbolAddress((void**)&p_dec,  g_dec);
    cudaGetSymbolAddress((void**)&p_decb, g_decb);
    cudaGetSymbolAddress((void**)&p_rb,   g_rb);
    cudaGetSymbolAddress((void**)&p_w,    g_wsp);
    cudaGetSymbolAddress((void**)&p_h,    g_hsp);
    cudaGetSymbolAddress((void**)&p_a,    g_asp);
    cudaGetSymbolAddress((void**)&p_c,    g_csp);
    cudaGetSymbolAddress((void**)&p_mf,   g_mfsp);

    cudaFuncSetAttribute(tgemm<0,0>, cudaFuncAttributeMaxDynamicSharedMemorySize, TG_SMEM);
    cudaFuncSetAttribute(tgemm<1,1>, cudaFuncAttributeMaxDynamicSharedMemorySize, TG_SMEM);

    const long AOB = (long)(APLANE * 2);
    const long MOB = (long)(MPLANE * 2);
    const long WOB = (long)(WPLANE * 2);

    // launch 0: bulk weight prep
    {
        PrepTab tab;
        int i = 0;
        auto add = [&](const float* s, int st, int dst) {
            tab.s[i].src = s; tab.s[i].stride = st; tab.s[i].dst = dst; tab.s[i].pad = 0; i++;
        };
        add(mol_al_w,      2*FF, W_MOL0);
        add(mol_al_w + FF, 2*FF, W_MOL1);
        add(mgru_wih,      FF,   W_MGI);
        add(mgru_whh,      FF,   W_MGH);
        for (int d = 0; d < RROUNDS; d++) {
            const float* aw = align_w + (size_t)d * FF * 2 * FF;
            add(aw,                             2*FF, W_RND(d) + 0);
            add(aw + FF,                        2*FF, W_RND(d) + 200);
            add(attend_w + (size_t)d * FF * FF, FF,   W_RND(d) + 400);
            add(gru_wih + (size_t)d * F3 * FF,  FF,   W_RND(d) + 600);
            add(gru_whh + (size_t)d * F3 * FF,  FF,   W_RND(d) + 1200);
        }
        prep_all<<<(W_DEC * KPAD + 255) / 256, 256>>>(tab);
    }
    // launch 1: fused mol_pre + remaining prep
    prep_rest_molpre<<<FUSE_BLKS, 256>>>(atom_fc_w, bond_fc_w,
                                         atom_fc_b, bond_fc_b,
                                         align_b, attend_b, molf, actf);

    #define WOFFP(o) (p_w + (size_t)(o) * KPAD)
    #define NODUAL nullptr, nullptr, nullptr, nullptr

    // launch 2: molW (tiny)
    tgemm<0,0><<<tg_grid(BB, FF), 256, TG_SMEM>>>(
        p_mf, WOFFP(W_MOL0), mol_al_b, p_molW, nullptr,
        BB, FF, nullptr, 1, MOB, WOB, 0, NODUAL);

    for (int t = 0; t < TSTEPS; t++) {
        tgemm<1,1><<<tg_grid(BL, FF), 256, TG_SMEM>>>(
            p_h, WOFFP(W_MOL1), nullptr, nullptr, p_c,
            BL, FF, p_molW, LL, AOB, WOB, (long)APLANE, NODUAL);
        tgemm<0,0><<<tg_grid(BL, F3, 2), 256, TG_SMEM>>>(
            p_c, WOFFP(W_MGI), mgru_bih, p_gi, nullptr,
            BL, F3, nullptr, 1, AOB, WOB, 0,
            p_h, WOFFP(W_MGH), mgru_bhh, p_gh);
        gru_combine_kernel<<<(BL * FF + 255) / 256, 256>>>(p_gi, p_gh, p_h, 1, BL * FF);
    }

    for (int d = 0; d < RROUNDS; d++) {
        tgemm<0,0><<<tg_grid(BL, F3), 256, TG_SMEM>>>(
            p_a, WOFFP(W_RND(d)), p_rb + (size_t)d * F3, p_sst, nullptr,
            BL, F3, nullptr, 1, AOB, WOB, 0, NODUAL);
        attn_ctx_kernel<<<BL, 256>>>(p_sst, deg);
        tgemm<0,0><<<tg_grid(BL, F3, 2), 256, TG_SMEM>>>(
            p_c, WOFFP(W_RND(d) + 600), gru_bih + (size_t)d * F3, p_gi, nullptr,
            BL, F3, nullptr, 1, AOB, WOB, 0,
            p_a, WOFFP(W_RND(d) + 1200), gru_bhh + (size_t)d * F3, p_gh);
        gru_combine_kernel<<<(BL * FF + 255) / 256, 256>>>(p_gi, p_gh, p_a, 0, BL * FF);
    }

    tgemm<0,0><<<tg_grid(BL, 64), 256, TG_SMEM>>>(
        p_a, WOFFP(W_DEC), p_decb, p_dec, nullptr,
        BL, 64, nullptr, 1, AOB, WOB, 0, NODUAL);

    atom_act_kernel<<<(BL + 255) / 256, 256>>>(p_dec, out, BL);
    bond_act_kernel<<<(BL * NNB + 255) / 256, 256>>>(p_dec, deg,
                                                     out + (size_t)BL * 39, BL * NNB);
}

// round 17
// speedup vs baseline: 3.1949x; 1.0532x over previous
#include <cuda_runtime.h>
#include <cuda_bf16.h>
#include <math.h>
#include <stdint.h>

#define BB 128
#define LL 256
#define NNB 8
#define FF 200
#define F3 600
#define BL (BB*LL)
#define RROUNDS 2
#define TSTEPS 2
#define KPAD 224
#define NCH 7

__device__ float g_molW[BB*FF];
__device__ float g_sst[BL*F3];
__device__ float g_gi[BL*F3];
__device__ float g_gh[BL*F3];
__device__ float g_dec[BL*64];
__device__ float g_decb[64];
__device__ float g_rb[RROUNDS*F3];

#define APLANE ((size_t)BL*KPAD)
#define MPLANE ((size_t)BB*KPAD)
__device__ __align__(16) __nv_bfloat16 g_hsp[2*BL*KPAD];
__device__ __align__(16) __nv_bfloat16 g_asp[2*BL*KPAD];
__device__ __align__(16) __nv_bfloat16 g_csp[2*BL*KPAD];
__device__ __align__(16) __nv_bfloat16 g_mfsp[2*BB*KPAD];

#define WROWS 5264
#define WPLANE ((size_t)WROWS*KPAD)
__device__ __align__(16) __nv_bfloat16 g_wsp[2*WROWS*KPAD];

#define W_MOL0 0
#define W_MOL1 200
#define W_MGI  400
#define W_MGH  1000
#define W_RND(d) (1600 + (d)*1800)
#define W_DEC  5200
#define NSEG 14

__device__ __forceinline__ uint32_t smem_u32(const void* p) {
    uint32_t a;
    asm("{ .reg .u64 t; cvta.to.shared.u64 t, %1; cvt.u32.u64 %0, t; }"
        : "=r"(a) : "l"(p));
    return a;
}
__device__ __forceinline__ void ldsm4(uint32_t* r, uint32_t a) {
    asm volatile("ldmatrix.sync.aligned.m8n8.x4.shared.b16 {%0,%1,%2,%3}, [%4];"
        : "=r"(r[0]), "=r"(r[1]), "=r"(r[2]), "=r"(r[3]) : "r"(a));
}
__device__ __forceinline__ void mma_bf16(float* c, const uint32_t* a, const uint32_t* b) {
    asm volatile("mma.sync.aligned.m16n8k16.row.col.f32.bf16.bf16.f32 "
        "{%0,%1,%2,%3}, {%4,%5,%6,%7}, {%8,%9}, {%0,%1,%2,%3};"
        : "+f"(c[0]), "+f"(c[1]), "+f"(c[2]), "+f"(c[3])
        : "r"(a[0]), "r"(a[1]), "r"(a[2]), "r"(a[3]), "r"(b[0]), "r"(b[1]));
}
__device__ __forceinline__ void cpa16(uint32_t dst, const void* src, int srcSize) {
    asm volatile("cp.async.cg.shared.global [%0], [%1], 16, %2;"
        :: "r"(dst), "l"(src), "r"(srcSize));
}
__device__ __forceinline__ void cp_commit() {
    asm volatile("cp.async.commit_group;" ::: "memory");
}
__device__ __forceinline__ void cp_wait1() {
    asm volatile("cp.async.wait_group 1;" ::: "memory");
}
__device__ __forceinline__ void split2(float v, __nv_bfloat16* hi, __nv_bfloat16* lo) {
    __nv_bfloat16 h = __float2bfloat16(v);
    *hi = h;
    *lo = __float2bfloat16(v - __bfloat162float(h));
}
// swizzled byte-offset within a rows x 64B region (conflict-free for ldsm octets)
__device__ __forceinline__ uint32_t swz(int row, int kbyte) {
    return (uint32_t)(row * 64) + ((uint32_t)(((kbyte >> 4) ^ ((row >> 1) & 3)) << 4));
}

// ---- fused weight prep ----
struct PrepSeg { const float* src; int stride; int dst; int pad; };
struct PrepTab { PrepSeg s[NSEG]; };

__global__ void prep_all(PrepTab tab)
{
    int idx = blockIdx.x * blockDim.x + threadIdx.x;
    if (idx >= W_DEC * KPAD) return;
    int r = idx / KPAD, k = idx - r * KPAD;
    int si = 0;
    #pragma unroll
    for (int i = 1; i < NSEG; i++) if (r >= tab.s[i].dst) si = i;
    const PrepSeg sg = tab.s[si];
    int lr = r - sg.dst;
    float x = (k < FF) ? sg.src[(size_t)lr * sg.stride + k] : 0.f;
    split2(x, &g_wsp[(size_t)r * KPAD + k], &g_wsp[WPLANE + (size_t)r * KPAD + k]);
}

#define REST_DEC (59*KPAD)
#define REST_MISC (64 + RROUNDS*F3)
#define REST_MOLF (BB*KPAD)
#define REST_TOT (REST_DEC + REST_MISC + REST_MOLF)
#define FUSE_BLKS (BB + (REST_TOT + 255) / 256)

__global__ __launch_bounds__(256) void prep_rest_molpre(
    const float* __restrict__ afw, const float* __restrict__ bfw,
    const float* __restrict__ ab,  const float* __restrict__ bb,
    const float* __restrict__ align_b, const float* __restrict__ attend_b,
    const float* __restrict__ molf, const float* __restrict__ actf)
{
    if (blockIdx.x < BB) {
        int b = blockIdx.x;
        int tid = threadIdx.x;
        __shared__ float dots[LL];
        __shared__ float red[16];
        const float* mf = molf + (size_t)b * FF;
        int lane = tid & 31, warp = tid >> 5;

        for (int l = warp; l < LL; l += 8) {
            const float* af = actf + ((size_t)b * LL + l) * FF;
            float s = 0.f;
            for (int f = lane; f < FF; f += 32) s += mf[f] * af[f];
            #pragma unroll
            for (int o = 16; o > 0; o >>= 1) s += __shfl_xor_sync(0xffffffffu, s, o);
            if (lane == 0) dots[l] = s;
        }
        __syncthreads();

        float v = dots[tid];
        float m = v;
        #pragma unroll
        for (int o = 16; o > 0; o >>= 1) m = fmaxf(m, __shfl_xor_sync(0xffffffffu, m, o));
        if (lane == 0) red[warp] = m;
        __syncthreads();
        float mx = red[0];
        #pragma unroll
        for (int i = 1; i < 8; i++) mx = fmaxf(mx, red[i]);
        float e = expf(v - mx);
        float s = e;
        #pragma unroll
        for (int o = 16; o > 0; o >>= 1) s += __shfl_xor_sync(0xffffffffu, s, o);
        if (lane == 0) red[8 + warp] = s;
        __syncthreads();
        float tot = 0.f;
        #pragma unroll
        for (int i = 0; i < 8; i++) tot += red[8 + i];
        __syncthreads();
        dots[tid] = e / tot;
        __syncthreads();

        size_t base = (size_t)b * LL * FF;
        for (int i = tid; i < LL * FF; i += 256) {
            int l = i / FF, f = i - l * FF;
            float v2 = dots[l] * mf[f] + actf[base + i];
            size_t si = ((size_t)b * LL + l) * KPAD + f;
            split2(v2, &g_hsp[si], &g_hsp[APLANE + si]);
        }
        return;
    }

    int idx = (blockIdx.x - BB) * 256 + threadIdx.x;
    if (idx < REST_DEC) {
        int r = idx / KPAD, k = idx - r * KPAD;
        float x = 0.f;
        if (k < FF) {
            if (r < 39)      x = afw[(size_t)r * FF + k];
            else if (r < 49) x = bfw[(size_t)(r - 39) * (2 * FF) + k];
            else             x = bfw[(size_t)(r - 49) * (2 * FF) + FF + k];
        }
        size_t rr = (size_t)(W_DEC + r) * KPAD + k;
        split2(x, &g_wsp[rr], &g_wsp[WPLANE + rr]);
        return;
    }
    idx -= REST_DEC;
    if (idx < REST_MISC) {
        if (idx < 64) {
            float v = 0.f;
            if (idx < 39) v = ab[idx];
            else if (idx < 49) v = bb[idx - 39];
            g_decb[idx] = v;
        } else {
            int j = idx - 64;
            int d = j / F3, f = j - d * F3;
            float v = 0.f;
            if (f < 200) v = align_b[d * FF + f];
            else if (f >= 400) v = attend_b[d * FF + f - 400];
            g_rb[j] = v;
        }
        return;
    }
    idx -= REST_MISC;
    if (idx < REST_MOLF) {
        int r = idx / KPAD, k = idx - r * KPAD;
        float x = (k < FF) ? molf[(size_t)r * FF + k] : 0.f;
        split2(x, &g_mfsp[idx], &g_mfsp[MPLANE + idx]);
    }
}

// ---- split-bf16 tensor GEMM: CTA 128x64, warp 32x32, 3-stage, 3 CTAs/SM ----
#define AREG 8192              // 128 rows * 64 B
#define RB_HI 16384
#define RB_LO 20480
#define STG 24576
#define NSTG 3
#define TG_SMEM (NSTG*STG)     // 73728

template<int ACT, int OUT>
__global__ __launch_bounds__(256, 3) void tgemm(
    const __nv_bfloat16* __restrict__ Ap0, const __nv_bfloat16* __restrict__ Wp0,
    const float* __restrict__ bias0, float* __restrict__ C0,
    __nv_bfloat16* __restrict__ Cp,
    int M, int Nn, const float* __restrict__ rowAdd, int rpg,
    long aOffB, long wOffB, long cOffE,
    const __nv_bfloat16* Ap1, const __nv_bfloat16* Wp1,
    const float* bias1, float* C1)
{
    extern __shared__ __align__(16) char sm[];
    const uint32_t sb = smem_u32(sm);
    const int tid = threadIdx.x, lane = tid & 31, wid = tid >> 5;
    const int bm = blockIdx.y * 128, bn = blockIdx.x * 64;
    const int wm = (wid & 3) * 32, wn = (wid >> 2) * 32;

    const __nv_bfloat16* Ap = Ap0;
    const __nv_bfloat16* Wp = Wp0;
    const float* bias = bias0;
    float* C = C0;
    if (blockIdx.z == 1) { Ap = Ap1; Wp = Wp1; bias = bias1; C = C1; }

    float acc[2][4][4];
    #pragma unroll
    for (int i = 0; i < 2; i++)
        #pragma unroll
        for (int j = 0; j < 4; j++)
            #pragma unroll
            for (int k = 0; k < 4; k++) acc[i][j][k] = 0.f;

    // loader: A rows r0 and r0+64 (16B granules); B row r0 (rows 0..63)
    const int r0 = tid >> 2, s0b = (tid & 3) * 16;
    const int r1 = r0 + 64;
    const int nBr = bn + r0;
    const int vBB = (nBr < Nn) ? 16 : 0;
    const int nBs = (nBr < Nn) ? nBr : 0;

    const char* pA0 = (const char*)(Ap + (size_t)(bm + r0) * KPAD) + s0b;
    const char* pA1 = (const char*)(Ap + (size_t)(bm + r1) * KPAD) + s0b;
    const char* pB  = (const char*)(Wp + (size_t)nBs * KPAD) + s0b;
    const uint32_t d0 = swz(r0, s0b);
    const uint32_t d1 = swz(r1, s0b);
    const uint32_t dB = d0;

    auto stage_load = [&](int t, int st) {
        const int kb = t * 64;
        const uint32_t s = sb + st * STG;
        cpa16(s + d0,          pA0 + kb, 16);
        cpa16(s + d1,          pA1 + kb, 16);
        cpa16(s + AREG + d0,   pA0 + aOffB + kb, 16);
        cpa16(s + AREG + d1,   pA1 + aOffB + kb, 16);
        cpa16(s + RB_HI + dB,  pB + kb, vBB);
        cpa16(s + RB_LO + dB,  pB + wOffB + kb, vBB);
    };

    stage_load(0, 0); cp_commit();
    stage_load(1, 1); cp_commit();

    const int arow = lane & 15;
    const int brow = lane & 7, sel = lane >> 3;
    const int nOff = (sel >> 1) * 8, kOff = (sel & 1) * 8;

    int st = 0;
    for (int t = 0; t < NCH; t++) {
        cp_wait1();
        __syncthreads();
        if (t + 2 < NCH) stage_load(t + 2, (st + 2) % NSTG);
        cp_commit();
        const uint32_t s = sb + st * STG;

        #pragma unroll
        for (int ks = 0; ks < 32; ks += 16) {
            uint32_t ah[2][4], al[2][4], bh[2][4], blo[2][4];
            const int akc = (ks + ((lane >> 4) << 3)) * 2;
            #pragma unroll
            for (int mi = 0; mi < 2; mi++) {
                uint32_t ad = s + swz(wm + mi * 16 + arow, akc);
                ldsm4(ah[mi], ad);
                ldsm4(al[mi], ad + AREG);
            }
            #pragma unroll
            for (int g = 0; g < 2; g++) {
                uint32_t bd = s + RB_HI + swz(wn + g * 16 + nOff + brow, (ks + kOff) * 2);
                ldsm4(bh[g], bd);
                ldsm4(blo[g], bd + (RB_LO - RB_HI));
            }
            #pragma unroll
            for (int mi = 0; mi < 2; mi++)
                #pragma unroll
                for (int nj = 0; nj < 4; nj++) {
                    const uint32_t* b2h = &bh[nj >> 1][(nj & 1) * 2];
                    const uint32_t* b2l = &blo[nj >> 1][(nj & 1) * 2];
                    float* a = acc[mi][nj];
                    mma_bf16(a, ah[mi], b2h);
                    mma_bf16(a, ah[mi], b2l);
                    mma_bf16(a, al[mi], b2h);
                }
        }
        st = (st + 1) % NSTG;
    }

    const int lr = lane >> 2, lc = (lane & 3) * 2;
    #pragma unroll
    for (int mi = 0; mi < 2; mi++) {
        #pragma unroll
        for (int hh = 0; hh < 2; hh++) {
            int m = bm + wm + mi * 16 + hh * 8 + lr;
            const float* ra = rowAdd ? (rowAdd + (size_t)(m / rpg) * Nn) : nullptr;
            #pragma unroll
            for (int nj = 0; nj < 4; nj++) {
                int n = bn + wn + nj * 8 + lc;
                if (n >= Nn) continue;
                float v0f = acc[mi][nj][hh * 2 + 0];
                float v1f = acc[mi][nj][hh * 2 + 1];
                if (bias) { v0f += bias[n]; v1f += bias[n + 1]; }
                if (ra)   { v0f += ra[n];   v1f += ra[n + 1]; }
                if (ACT == 1) { v0f = (v0f > 0.f) ? v0f : expm1f(v0f);
                                v1f = (v1f > 0.f) ? v1f : expm1f(v1f); }
                else if (ACT == 2) { v0f = fmaxf(v0f, 0.f); v1f = fmaxf(v1f, 0.f); }
                if (OUT == 0) {
                    *(float2*)&C[(size_t)m * Nn + n] = make_float2(v0f, v1f);
                } else {
                    __nv_bfloat162 h2 = __floats2bfloat162_rn(v0f, v1f);
                    __nv_bfloat162 l2 = __floats2bfloat162_rn(
                        v0f - __bfloat162float(h2.x), v1f - __bfloat162float(h2.y));
                    size_t ci = (size_t)m * KPAD + n;
                    *(__nv_bfloat162*)&Cp[ci] = h2;
                    *(__nv_bfloat162*)&Cp[cOffE + ci] = l2;
                }
            }
        }
    }
}

__global__ __launch_bounds__(256) void gru_combine_kernel(
    const float* __restrict__ gi, const float* __restrict__ gh,
    const __nv_bfloat16* __restrict__ hsp, int writeH, int total)
{
    int idx = blockIdx.x * blockDim.x + threadIdx.x;
    if (idx >= total) return;
    int m = idx / FF, f = idx - m * FF;
    size_t b3 = (size_t)m * F3;
    float ir = gi[b3 + f], iz = gi[b3 + FF + f], in_ = gi[b3 + 2 * FF + f];
    float hr = gh[b3 + f], hz = gh[b3 + FF + f], hn = gh[b3 + 2 * FF + f];
    float r = 1.f / (1.f + expf(-(ir + hr)));
    float z = 1.f / (1.f + expf(-(iz + hz)));
    float n = tanhf(in_ + r * hn);
    size_t si = (size_t)m * KPAD + f;
    float h = __bfloat162float(hsp[si]) + __bfloat162float(hsp[APLANE + si]);
    float o = (1.f - z) * n + z * h;
    if (writeH) split2(o, &g_hsp[si], &g_hsp[APLANE + si]);
    float a = fmaxf(o, 0.f);
    split2(a, &g_asp[si], &g_asp[APLANE + si]);
}

__global__ __launch_bounds__(256) void attn_ctx_kernel(
    const float* __restrict__ sst, const int* __restrict__ deg)
{
    int bl = blockIdx.x;
    int b = bl >> 8;
    int tid = threadIdx.x;
    __shared__ int sidx[NNB];
    if (tid < NNB) sidx[tid] = deg[(size_t)bl * NNB + tid];
    __syncthreads();
    if (tid >= FF) return;
    int f = tid;
    float s1v = sst[(size_t)bl * F3 + f];
    float sc[NNB];
    float mx = -3.4e38f;
    #pragma unroll
    for (int n = 0; n < NNB; n++) {
        int j = sidx[n];
        float v = s1v + sst[((size_t)b * LL + j) * F3 + 200 + f];
        v = (v >= 0.f) ? v : 0.01f * v;
        if (j == LL - 1) v += -9e8f;
        sc[n] = v;
        mx = fmaxf(mx, v);
    }
    float sum = 0.f;
    #pragma unroll
    for (int n = 0; n < NNB; n++) { sc[n] = expf(sc[n] - mx); sum += sc[n]; }
    float inv = 1.f / sum;
    float c = 0.f;
    #pragma unroll
    for (int n = 0; n < NNB; n++) {
        int j = sidx[n];
        if (j != LL - 1)
            c += sc[n] * inv * sst[((size_t)b * LL + j) * F3 + 400 + f];
    }
    c = (c > 0.f) ? c : expm1f(c);
    size_t si = (size_t)bl * KPAD + f;
    split2(c, &g_csp[si], &g_csp[APLANE + si]);
}

__device__ __forceinline__ void seg_softmax_acc(const float* v, float* y, int lo, int hi) {
    float m = -3.4e38f;
    for (int i = lo; i < hi; i++) m = fmaxf(m, v[i]);
    float s = 0.f;
    for (int i = lo; i < hi; i++) s += expf(v[i] - m);
    float inv = 1.f / s;
    for (int i = lo; i < hi; i++) y[i] += expf(v[i] - m) * inv;
}
__device__ __forceinline__ float sigf(float x) { return 1.f / (1.f + expf(-x)); }

__global__ __launch_bounds__(256) void atom_act_kernel(
    const float* __restrict__ dec, float* __restrict__ out, int rows)
{
    int m = blockIdx.x * blockDim.x + threadIdx.x;
    if (m >= rows) return;
    const float* x = dec + (size_t)m * 64;
    float v[39], y[39];
    #pragma unroll
    for (int i = 0; i < 39; i++) { v[i] = x[i]; y[i] = 0.f; }
    seg_softmax_acc(v, y, 0, 16);
    seg_softmax_acc(v, y, 16, 22);
    seg_softmax_acc(v, y, 24, 30);
    seg_softmax_acc(v, y, 31, 36);
    y[24] += fmaxf(v[24], 0.f);
    y[30] += sigf(v[30]);
    y[36] += sigf(v[36]);
    y[37] += sigf(v[37]);
    y[38] += sigf(v[38]);
    float* o = out + (size_t)m * 39;
    #pragma unroll
    for (int i = 0; i < 39; i++) o[i] = y[i];
}

__global__ __launch_bounds__(256) void bond_act_kernel(
    const float* __restrict__ dec, const int* __restrict__ deg,
    float* __restrict__ out, int total)
{
    int id = blockIdx.x * blockDim.x + threadIdx.x;
    if (id >= total) return;
    int bl = id / NNB;
    int b = bl >> 8;
    int j = deg[id];
    const float* a = dec + (size_t)bl * 64 + 39;
    const float* c = dec + ((size_t)b * LL + j) * 64 + 49;
    float v[10], y[10];
    #pragma unroll
    for (int k = 0; k < 10; k++) { v[k] = a[k] + c[k]; y[k] = 0.f; }
    seg_softmax_acc(v, y, 0, 4);
    seg_softmax_acc(v, y, 6, 10);
    y[4] += sigf(v[4]);
    y[5] += sigf(v[5]);
    float* o = out + (size_t)id * 10;
    #pragma unroll
    for (int k = 0; k < 10; k++) o[k] = y[k];
}

static inline dim3 tg_grid(int M, int N, int z = 1) {
    return dim3((N + 63) / 64, M / 128, z);
}

extern "C" void kernel_launch(void* const* d_in, const int* in_sizes, int n_in,
                              void* d_out, int out_size)
{
    const int*   deg        = (const int*)  d_in[2];
    const float* molf       = (const float*)d_in[5];
    const float* actf       = (const float*)d_in[6];
    const float* atom_fc_w  = (const float*)d_in[7];
    const float* atom_fc_b  = (const float*)d_in[8];
    const float* bond_fc_w  = (const float*)d_in[9];
    const float* bond_fc_b  = (const float*)d_in[10];
    const float* align_w    = (const float*)d_in[11];
    const float* align_b    = (const float*)d_in[12];
    const float* attend_w   = (const float*)d_in[13];
    const float* attend_b   = (const float*)d_in[14];
    const float* gru_wih    = (const float*)d_in[15];
    const float* gru_whh    = (const float*)d_in[16];
    const float* gru_bih    = (const float*)d_in[17];
    const float* gru_bhh    = (const float*)d_in[18];
    const float* mol_al_w   = (const float*)d_in[19];
    const float* mol_al_b   = (const float*)d_in[20];
    const float* mgru_wih   = (const float*)d_in[21];
    const float* mgru_whh   = (const float*)d_in[22];
    const float* mgru_bih   = (const float*)d_in[23];
    const float* mgru_bhh   = (const float*)d_in[24];
    float* out = (float*)d_out;

    float *p_molW, *p_sst, *p_gi, *p_gh, *p_dec, *p_decb, *p_rb;
    __nv_bfloat16 *p_w, *p_h, *p_a, *p_c, *p_mf;
    cudaGetSymbolAddress((void**)&p_molW, g_molW);
    cudaGetSymbolAddress((void**)&p_sst,  g_sst);
    cudaGetSymbolAddress((void**)&p_gi,   g_gi);
    cudaGetSymbolAddress((void**)&p_gh,   g_gh);
    cudaGetSymbolAddress((void**)&p_dec,  g_dec);
    cudaGetSymbolAddress((void**)&p_decb, g_decb);
    cudaGetSymbolAddress((void**)&p_rb,   g_rb);
    cudaGetSymbolAddress((void**)&p_w,    g_wsp);
    cudaGetSymbolAddress((void**)&p_h,    g_hsp);
    cudaGetSymbolAddress((void**)&p_a,    g_asp);
    cudaGetSymbolAddress((void**)&p_c,    g_csp);
    cudaGetSymbolAddress((void**)&p_mf,   g_mfsp);

    cudaFuncSetAttribute(tgemm<0,0>, cudaFuncAttributeMaxDynamicSharedMemorySize, TG_SMEM);
    cudaFuncSetAttribute(tgemm<1,1>, cudaFuncAttributeMaxDynamicSharedMemorySize, TG_SMEM);

    const long AOB = (long)(APLANE * 2);
    const long MOB = (long)(MPLANE * 2);
    const long WOB = (long)(WPLANE * 2);

    // launch 0: bulk weight prep
    {
        PrepTab tab;
        int i = 0;
        auto add = [&](const float* s, int st, int dst) {
            tab.s[i].src = s; tab.s[i].stride = st; tab.s[i].dst = dst; tab.s[i].pad = 0; i++;
        };
        add(mol_al_w,      2*FF, W_MOL0);
        add(mol_al_w + FF, 2*FF, W_MOL1);
        add(mgru_wih,      FF,   W_MGI);
        add(mgru_whh,      FF,   W_MGH);
        for (int d = 0; d < RROUNDS; d++) {
            const float* aw = align_w + (size_t)d * FF * 2 * FF;
            add(aw,                             2*FF, W_RND(d) + 0);
            add(aw + FF,                        2*FF, W_RND(d) + 200);
            add(attend_w + (size_t)d * FF * FF, FF,   W_RND(d) + 400);
            add(gru_wih + (size_t)d * F3 * FF,  FF,   W_RND(d) + 600);
            add(gru_whh + (size_t)d * F3 * FF,  FF,   W_RND(d) + 1200);
        }
        prep_all<<<(W_DEC * KPAD + 255) / 256, 256>>>(tab);
    }
    // launch 1: fused mol_pre + remaining prep
    prep_rest_molpre<<<FUSE_BLKS, 256>>>(atom_fc_w, bond_fc_w,
                                         atom_fc_b, bond_fc_b,
                                         align_b, attend_b, molf, actf);

    #define WOFFP(o) (p_w + (size_t)(o) * KPAD)
    #define NODUAL nullptr, nullptr, nullptr, nullptr

    // launch 2: molW (tiny)
    tgemm<0,0><<<tg_grid(BB, FF), 256, TG_SMEM>>>(
        p_mf, WOFFP(W_MOL0), mol_al_b, p_molW, nullptr,
        BB, FF, nullptr, 1, MOB, WOB, 0, NODUAL);

    for (int t = 0; t < TSTEPS; t++) {
        tgemm<1,1><<<tg_grid(BL, FF), 256, TG_SMEM>>>(
            p_h, WOFFP(W_MOL1), nullptr, nullptr, p_c,
            BL, FF, p_molW, LL, AOB, WOB, (long)APLANE, NODUAL);
        tgemm<0,0><<<tg_grid(BL, F3, 2), 256, TG_SMEM>>>(
            p_c, WOFFP(W_MGI), mgru_bih, p_gi, nullptr,
            BL, F3, nullptr, 1, AOB, WOB, 0,
            p_h, WOFFP(W_MGH), mgru_bhh, p_gh);
        gru_combine_kernel<<<(BL * FF + 255) / 256, 256>>>(p_gi, p_gh, p_h, 1, BL * FF);
    }

    for (int d = 0; d < RROUNDS; d++) {
        tgemm<0,0><<<tg_grid(BL, F3), 256, TG_SMEM>>>(
            p_a, WOFFP(W_RND(d)), p_rb + (size_t)d * F3, p_sst, nullptr,
            BL, F3, nullptr, 1, AOB, WOB, 0, NODUAL);
        attn_ctx_kernel<<<BL, 256>>>(p_sst, deg);
        tgemm<0,0><<<tg_grid(BL, F3, 2), 256, TG_SMEM>>>(
            p_c, WOFFP(W_RND(d) + 600), gru_bih + (size_t)d * F3, p_gi, nullptr,
            BL, F3, nullptr, 1, AOB, WOB, 0,
            p_a, WOFFP(W_RND(d) + 1200), gru_bhh + (size_t)d * F3, p_gh);
        gru_combine_kernel<<<(BL * FF + 255) / 256, 256>>>(p_gi, p_gh, p_a, 0, BL * FF);
    }

    tgemm<0,0><<<tg_grid(BL, 64), 256, TG_SMEM>>>(
        p_a, WOFFP(W_DEC), p_decb, p_dec, nullptr,
        BL, 64, nullptr, 1, AOB, WOB, 0, NODUAL);

    atom_act_kernel<<<(BL + 255) / 256, 256>>>(p_dec, out, BL);
    bond_act_kernel<<<(BL * NNB + 255) / 256, 256>>>(p_dec, deg,
                                                     out + (size_t)BL * 39, BL * NNB);
}